// round 8
// baseline (speedup 1.0000x reference)
#include <cuda_runtime.h>

#define Bz 8
#define L0c 384
#define Lr 385
#define LP 448
#define Dm 128
#define NH 8
#define NIT 4

// ---------------- scratch ----------------
__device__ float g_unary[Bz*LP*Dm];
__device__ float g_qz[Bz*LP*Dm];
__device__ float g_P[(Bz*LP + 128)*Dm];
__device__ float g_m1[Bz*LP];
__device__ float g_Tu[2*Dm*NH*Dm];        // [k][a][c][b]
__device__ float g_Tv[2*Dm*NH*Dm];        // [k][b][c][a]
__device__ float g_U[Bz*2*LP*NH*Dm];      // [z][g][i][(c,b)] stacked m=(i*8+c)
__device__ float g_V[Bz*2*LP*NH*Dm];      // [z][g][j][(c,a)]
__device__ float g_Hmat[(size_t)Bz*NH*LP*LP];
__device__ float g_Gp[Bz*NH*LP*Dm];
__device__ float g_Hp[Bz*NH*LP*Dm];

// ---------------- tf32 helpers ----------------
__device__ __forceinline__ float tf32r(float x) {
    unsigned u;
    asm("cvt.rna.tf32.f32 %0, %1;" : "=r"(u) : "f"(x));
    return __uint_as_float(u);
}
__device__ __forceinline__ void split2(float x, float& h, float& l) {
    h = tf32r(x);
    l = tf32r(x - h);
}
__device__ __forceinline__ void mma8(float* c, const unsigned* a, const unsigned* b) {
    asm volatile(
        "mma.sync.aligned.m16n8k8.row.col.f32.tf32.tf32.f32 "
        "{%0,%1,%2,%3}, {%4,%5,%6,%7}, {%8,%9}, {%0,%1,%2,%3};"
        : "+f"(c[0]), "+f"(c[1]), "+f"(c[2]), "+f"(c[3])
        : "r"(a[0]), "r"(a[1]), "r"(a[2]), "r"(a[3]), "r"(b[0]), "r"(b[1]));
}

// ---------------- prep ----------------
__global__ void prep_unary_kernel(const float* __restrict__ x,
                                  const float* __restrict__ mask) {
    int idx = blockIdx.x * blockDim.x + threadIdx.x;
    if (idx >= Bz*LP*Dm) return;
    int d = idx & 127;
    int zi = idx >> 7;
    int i = zi % LP, z = zi / LP;
    float v = 0.f;
    if (i >= 1 && i < Lr) v = x[(z*L0c + (i-1))*Dm + d];
    float m = (i == 0) ? 1.f : ((i < Lr) ? mask[z*L0c + (i-1)] : 0.f);
    g_unary[idx] = v;
    g_qz[idx]    = v * m;
    g_P[idx]     = 0.f;
    if (d == 0) g_m1[zi] = m;
}

__global__ void zero_ppad_kernel() {
    int idx = blockIdx.x * blockDim.x + threadIdx.x;
    if (idx < 128*Dm) g_P[Bz*LP*Dm + idx] = 0.f;
}

__global__ void prep_T_kernel(const float* __restrict__ tern) {
    int idx = blockIdx.x * blockDim.x + threadIdx.x;
    if (idx >= 2*Dm*Dm*NH) return;
    int c = idx & 7;
    int r = idx >> 3;
    int b = r & 127; r >>= 7;
    int a = r & 127;
    int k = r >> 7;
    float v = tern[idx];
    g_Tu[((k*Dm + a)*NH + c)*Dm + b] = v;
    g_Tv[((k*Dm + b)*NH + c)*Dm + a] = v;
}

// ---------------- softmax over d ----------------
__global__ void softmax_p_kernel() {
    int row = blockIdx.x;
    int z = row / Lr, i = row - z*Lr;
    const float* src = g_qz + (z*LP + i)*Dm;
    int t = threadIdx.x;
    float v = src[t];
    __shared__ float shm[4], shs[4];
    float m = v;
#pragma unroll
    for (int o = 16; o; o >>= 1) m = fmaxf(m, __shfl_xor_sync(0xffffffffu, m, o));
    if ((t & 31) == 0) shm[t >> 5] = m;
    __syncthreads();
    m = fmaxf(fmaxf(shm[0], shm[1]), fmaxf(shm[2], shm[3]));
    float e = __expf(v - m);
    float s = e;
#pragma unroll
    for (int o = 16; o; o >>= 1) s += __shfl_xor_sync(0xffffffffu, s, o);
    if ((t & 31) == 0) shs[t >> 5] = s;
    __syncthreads();
    s = (shs[0] + shs[1]) + (shs[2] + shs[3]);
    g_P[(z*LP + i)*Dm + t] = e / s * g_m1[z*LP + i];
}

// =============== UV (3xTF32 MMA): C[448x1024] = P @ T, tile 64x128, warps 2x4 ===============
__global__ __launch_bounds__(256) void gemm_uv_kernel() {
    int inst = blockIdx.z;
    int uv = inst & 1, kg = (inst >> 1) & 1, z = inst >> 2;
    const float* A  = g_P + (size_t)(z*LP)*Dm;
    const float* Bm = (uv ? g_Tv : g_Tu) + kg * (Dm*NH*Dm);
    float*       C  = (uv ? g_V : g_U) + (size_t)(z*2 + kg) * (LP*NH*Dm);
    int m0 = blockIdx.y * 64, n0 = blockIdx.x * 128;
    __shared__ float Ah[64*20], Al[64*20];
    __shared__ float Bh[16*136], Bl[16*136];
    int t = threadIdx.x, lane = t & 31, warp = t >> 5;
    int wm = (warp >> 2) * 32, wn = (warp & 3) * 32;
    int am = t >> 2, ak = (t & 3) << 2;
    int bk = t >> 4, bn = (t & 15) << 3;
    float acc[2][4][4] = {};
    float4 pa = *(const float4*)&A[(m0 + am)*Dm + ak];
    float4 pb0 = *(const float4*)&Bm[bk*1024 + n0 + bn];
    float4 pb1 = *(const float4*)&Bm[bk*1024 + n0 + bn + 4];
    for (int s = 0; s < 8; s++) {
        {
            float h, l;
            split2(pa.x, h, l); Ah[am*20+ak+0]=h; Al[am*20+ak+0]=l;
            split2(pa.y, h, l); Ah[am*20+ak+1]=h; Al[am*20+ak+1]=l;
            split2(pa.z, h, l); Ah[am*20+ak+2]=h; Al[am*20+ak+2]=l;
            split2(pa.w, h, l); Ah[am*20+ak+3]=h; Al[am*20+ak+3]=l;
            split2(pb0.x, h, l); Bh[bk*136+bn+0]=h; Bl[bk*136+bn+0]=l;
            split2(pb0.y, h, l); Bh[bk*136+bn+1]=h; Bl[bk*136+bn+1]=l;
            split2(pb0.z, h, l); Bh[bk*136+bn+2]=h; Bl[bk*136+bn+2]=l;
            split2(pb0.w, h, l); Bh[bk*136+bn+3]=h; Bl[bk*136+bn+3]=l;
            split2(pb1.x, h, l); Bh[bk*136+bn+4]=h; Bl[bk*136+bn+4]=l;
            split2(pb1.y, h, l); Bh[bk*136+bn+5]=h; Bl[bk*136+bn+5]=l;
            split2(pb1.z, h, l); Bh[bk*136+bn+6]=h; Bl[bk*136+bn+6]=l;
            split2(pb1.w, h, l); Bh[bk*136+bn+7]=h; Bl[bk*136+bn+7]=l;
        }
        __syncthreads();
        if (s < 7) {
            int kt = (s + 1) << 4;
            pa  = *(const float4*)&A[(m0 + am)*Dm + kt + ak];
            pb0 = *(const float4*)&Bm[(kt + bk)*1024 + n0 + bn];
            pb1 = *(const float4*)&Bm[(kt + bk)*1024 + n0 + bn + 4];
        }
#pragma unroll
        for (int k8 = 0; k8 < 16; k8 += 8) {
            int kk = k8 + (lane & 3);
            unsigned afh[2][4], afl[2][4], bfh[4][2], bfl[4][2];
#pragma unroll
            for (int tm = 0; tm < 2; tm++) {
                int r = wm + tm*16 + (lane >> 2);
                afh[tm][0] = __float_as_uint(Ah[r*20 + kk]);
                afh[tm][1] = __float_as_uint(Ah[(r+8)*20 + kk]);
                afh[tm][2] = __float_as_uint(Ah[r*20 + kk + 4]);
                afh[tm][3] = __float_as_uint(Ah[(r+8)*20 + kk + 4]);
                afl[tm][0] = __float_as_uint(Al[r*20 + kk]);
                afl[tm][1] = __float_as_uint(Al[(r+8)*20 + kk]);
                afl[tm][2] = __float_as_uint(Al[r*20 + kk + 4]);
                afl[tm][3] = __float_as_uint(Al[(r+8)*20 + kk + 4]);
            }
#pragma unroll
            for (int tn = 0; tn < 4; tn++) {
                int cn = wn + tn*8 + (lane >> 2);
                bfh[tn][0] = __float_as_uint(Bh[kk*136 + cn]);
                bfh[tn][1] = __float_as_uint(Bh[(kk+4)*136 + cn]);
                bfl[tn][0] = __float_as_uint(Bl[kk*136 + cn]);
                bfl[tn][1] = __float_as_uint(Bl[(kk+4)*136 + cn]);
            }
#pragma unroll
            for (int tm = 0; tm < 2; tm++)
#pragma unroll
                for (int tn = 0; tn < 4; tn++) {
                    mma8(acc[tm][tn], afl[tm], bfh[tn]);
                    mma8(acc[tm][tn], afh[tm], bfl[tn]);
                    mma8(acc[tm][tn], afh[tm], bfh[tn]);
                }
        }
        __syncthreads();
    }
#pragma unroll
    for (int tm = 0; tm < 2; tm++)
#pragma unroll
        for (int tn = 0; tn < 4; tn++) {
            int r  = m0 + wm + tm*16 + (lane >> 2);
            int cn = n0 + wn + tn*8 + 2*(lane & 3);
            *(float2*)&C[(size_t)r*1024 + cn]     = make_float2(acc[tm][tn][0], acc[tm][tn][1]);
            *(float2*)&C[(size_t)(r+8)*1024 + cn] = make_float2(acc[tm][tn][2], acc[tm][tn][3]);
        }
}

// =============== F (3xTF32): C[m=3584 x j=448] = U[m][b].P[j][b] NT, tile 128x64, warps 4x2 ===============
__global__ __launch_bounds__(256) void gemm_f_kernel() {
    int z = blockIdx.z;
    int m0 = blockIdx.y * 128, j0 = blockIdx.x * 64;
    int ilo = m0 >> 3;
    int mode = (j0 >= ilo + 16) ? 0 : ((j0 + 64 <= ilo) ? 1 : 2);
    __shared__ float Ah[128*20], Al[128*20];
    __shared__ float Ph[64*20],  Pl[64*20];
    int t = threadIdx.x, lane = t & 31, warp = t >> 5;
    int wm = (warp >> 1) * 32, wn = (warp & 1) * 32;
    int am = t >> 1, ah8 = (t & 1) << 3;
    int jr = t >> 2, bq = (t & 3) << 2;
    const float* Bp = g_P + (size_t)(z*LP)*Dm;
    int npass = (mode == 2) ? 2 : 1;
    for (int p = 0; p < npass; p++) {
        int g = (mode == 2) ? p : mode;
        const float* Au = g_U + (size_t)(z*2 + g)*(LP*NH*Dm);
        float acc[2][4][4] = {};
        float4 pa0 = *(const float4*)&Au[(size_t)(m0+am)*Dm + ah8];
        float4 pa1 = *(const float4*)&Au[(size_t)(m0+am)*Dm + ah8 + 4];
        float4 pb  = *(const float4*)&Bp[(size_t)(j0+jr)*Dm + bq];
        for (int s = 0; s < 8; s++) {
            {
                float h, l;
                split2(pa0.x, h, l); Ah[am*20+ah8+0]=h; Al[am*20+ah8+0]=l;
                split2(pa0.y, h, l); Ah[am*20+ah8+1]=h; Al[am*20+ah8+1]=l;
                split2(pa0.z, h, l); Ah[am*20+ah8+2]=h; Al[am*20+ah8+2]=l;
                split2(pa0.w, h, l); Ah[am*20+ah8+3]=h; Al[am*20+ah8+3]=l;
                split2(pa1.x, h, l); Ah[am*20+ah8+4]=h; Al[am*20+ah8+4]=l;
                split2(pa1.y, h, l); Ah[am*20+ah8+5]=h; Al[am*20+ah8+5]=l;
                split2(pa1.z, h, l); Ah[am*20+ah8+6]=h; Al[am*20+ah8+6]=l;
                split2(pa1.w, h, l); Ah[am*20+ah8+7]=h; Al[am*20+ah8+7]=l;
                split2(pb.x, h, l); Ph[jr*20+bq+0]=h; Pl[jr*20+bq+0]=l;
                split2(pb.y, h, l); Ph[jr*20+bq+1]=h; Pl[jr*20+bq+1]=l;
                split2(pb.z, h, l); Ph[jr*20+bq+2]=h; Pl[jr*20+bq+2]=l;
                split2(pb.w, h, l); Ph[jr*20+bq+3]=h; Pl[jr*20+bq+3]=l;
            }
            __syncthreads();
            if (s < 7) {
                int kt = (s + 1) << 4;
                pa0 = *(const float4*)&Au[(size_t)(m0+am)*Dm + kt + ah8];
                pa1 = *(const float4*)&Au[(size_t)(m0+am)*Dm + kt + ah8 + 4];
                pb  = *(const float4*)&Bp[(size_t)(j0+jr)*Dm + kt + bq];
            }
#pragma unroll
            for (int k8 = 0; k8 < 16; k8 += 8) {
                int kk = k8 + (lane & 3);
                unsigned afh[2][4], afl[2][4], bfh[4][2], bfl[4][2];
#pragma unroll
                for (int tm = 0; tm < 2; tm++) {
                    int r = wm + tm*16 + (lane >> 2);
                    afh[tm][0] = __float_as_uint(Ah[r*20 + kk]);
                    afh[tm][1] = __float_as_uint(Ah[(r+8)*20 + kk]);
                    afh[tm][2] = __float_as_uint(Ah[r*20 + kk + 4]);
                    afh[tm][3] = __float_as_uint(Ah[(r+8)*20 + kk + 4]);
                    afl[tm][0] = __float_as_uint(Al[r*20 + kk]);
                    afl[tm][1] = __float_as_uint(Al[(r+8)*20 + kk]);
                    afl[tm][2] = __float_as_uint(Al[r*20 + kk + 4]);
                    afl[tm][3] = __float_as_uint(Al[(r+8)*20 + kk + 4]);
                }
#pragma unroll
                for (int tn = 0; tn < 4; tn++) {
                    int cn = wn + tn*8 + (lane >> 2);
                    bfh[tn][0] = __float_as_uint(Ph[cn*20 + kk]);
                    bfh[tn][1] = __float_as_uint(Ph[cn*20 + kk + 4]);
                    bfl[tn][0] = __float_as_uint(Pl[cn*20 + kk]);
                    bfl[tn][1] = __float_as_uint(Pl[cn*20 + kk + 4]);
                }
#pragma unroll
                for (int tm = 0; tm < 2; tm++)
#pragma unroll
                    for (int tn = 0; tn < 4; tn++) {
                        mma8(acc[tm][tn], afl[tm], bfh[tn]);
                        mma8(acc[tm][tn], afh[tm], bfl[tn]);
                        mma8(acc[tm][tn], afh[tm], bfh[tn]);
                    }
            }
            __syncthreads();
        }
#pragma unroll
        for (int tm = 0; tm < 2; tm++)
#pragma unroll
            for (int tn = 0; tn < 4; tn++) {
                int jc = j0 + wn + tn*8 + 2*(lane & 3);
#pragma unroll
                for (int half = 0; half < 2; half++) {
                    int m = m0 + wm + tm*16 + (lane >> 2) + half*8;
                    int i = m >> 3, cc = m & 7;
                    size_t off = ((size_t)(z*NH + cc)*LP + i)*LP + jc;
                    float v0 = acc[tm][tn][half*2], v1 = acc[tm][tn][half*2 + 1];
                    if (mode != 2) {
                        *(float2*)&g_Hmat[off] = make_float2(v0, v1);
                    } else if (p == 0) {
                        *(float2*)&g_Hmat[off] = make_float2(jc > i ? v0 : 0.f,
                                                             jc + 1 > i ? v1 : 0.f);
                    } else {
                        if (jc     < i) g_Hmat[off]     = v0;
                        if (jc + 1 < i) g_Hmat[off + 1] = v1;
                    }
                }
            }
    }
}

// ---------------- H softmax over j ----------------
__global__ void hsoftmax_kernel() {
    int bid = blockIdx.x;
    int i = bid % Lr;
    int zc = bid / Lr;
    int z = zc >> 3;
    float* row = g_Hmat + (size_t)zc * (LP*LP) + (size_t)i * LP;
    int t = threadIdx.x;
    if (i == 0) {
        for (int j = t; j < Lr; j += 128) row[j] = 0.f;
        return;
    }
    float mi = g_m1[z*LP + i];
    float lv[4];
    float mx = -3.4e38f;
#pragma unroll
    for (int r = 0; r < 4; r++) {
        int j = t + r*128;
        float l = -3.4e38f;
        if (j < Lr) {
            bool ok = (mi != 0.f) && (g_m1[z*LP + j] != 0.f) && (j != i);
            l = ok ? row[j] * 128.f : -1e9f;
        }
        lv[r] = l;
        mx = fmaxf(mx, l);
    }
    __shared__ float shm[4], shs[4];
#pragma unroll
    for (int o = 16; o; o >>= 1) mx = fmaxf(mx, __shfl_xor_sync(0xffffffffu, mx, o));
    if ((t & 31) == 0) shm[t >> 5] = mx;
    __syncthreads();
    mx = fmaxf(fmaxf(shm[0], shm[1]), fmaxf(shm[2], shm[3]));
    float ev[4];
    float s = 0.f;
#pragma unroll
    for (int r = 0; r < 4; r++) {
        int j = t + r*128;
        ev[r] = 0.f;
        if (j < Lr) { ev[r] = __expf(lv[r] - mx); s += ev[r]; }
    }
#pragma unroll
    for (int o = 16; o; o >>= 1) s += __shfl_xor_sync(0xffffffffu, s, o);
    if ((t & 31) == 0) shs[t >> 5] = s;
    __syncthreads();
    s = (shs[0] + shs[1]) + (shs[2] + shs[3]);
    float inv = 1.f / s;
#pragma unroll
    for (int r = 0; r < 4; r++) {
        int j = t + r*128;
        if (j < Lr) row[j] = ev[r] * inv;
    }
}

// =============== G (3xTF32): C[i 64 x a 128] = Hsel @ V, tile 64x128, warps 2x4 ===============
__global__ __launch_bounds__(256) void gemm_g_kernel() {
    int c = blockIdx.x, i0 = blockIdx.y * 64, z = blockIdx.z;
    const float* Hmp = g_Hmat + (size_t)(z*NH + c) * (LP*LP);
    __shared__ float Ah[64*20], Al[64*20];
    __shared__ float Bh[16*136], Bl[16*136];
    int t = threadIdx.x, lane = t & 31, warp = t >> 5;
    int wm = (warp >> 2) * 32, wn = (warp & 3) * 32;
    int ir = t >> 2, jq = (t & 3) << 2;
    int bk = t >> 4, bn = (t & 15) << 3;
    float acc[2][4][4] = {};
    for (int ss = 0; ss < 28; ss++) {
        int j0s = ss << 4;
        int mode = (j0s >= i0 + 64) ? 0 : ((j0s + 16 <= i0) ? 1 : 2);
        int npass = (mode == 2) ? 2 : 1;
        float4 hv = *(const float4*)&Hmp[(size_t)(i0 + ir)*LP + j0s + jq];
        float h4[4] = {hv.x, hv.y, hv.z, hv.w};
        for (int p = 0; p < npass; p++) {
            int g = (mode == 2) ? p : mode;
            int ig = i0 + ir;
#pragma unroll
            for (int q = 0; q < 4; q++) {
                float val = h4[q];
                if (mode == 2) {
                    int jg = j0s + jq + q;
                    bool keep = (g == 0) ? (jg > ig) : (jg < ig);
                    if (!keep) val = 0.f;
                }
                float h, l;
                split2(val, h, l);
                Ah[ir*20 + jq + q] = h;
                Al[ir*20 + jq + q] = l;
            }
            const float* Vp = g_V + (size_t)(z*2 + g)*(LP*NH*Dm)
                             + (size_t)(j0s + bk)*1024 + c*Dm + bn;
            float4 v0 = *(const float4*)&Vp[0];
            float4 v1 = *(const float4*)&Vp[4];
            {
                float h, l;
                split2(v0.x, h, l); Bh[bk*136+bn+0]=h; Bl[bk*136+bn+0]=l;
                split2(v0.y, h, l); Bh[bk*136+bn+1]=h; Bl[bk*136+bn+1]=l;
                split2(v0.z, h, l); Bh[bk*136+bn+2]=h; Bl[bk*136+bn+2]=l;
                split2(v0.w, h, l); Bh[bk*136+bn+3]=h; Bl[bk*136+bn+3]=l;
                split2(v1.x, h, l); Bh[bk*136+bn+4]=h; Bl[bk*136+bn+4]=l;
                split2(v1.y, h, l); Bh[bk*136+bn+5]=h; Bl[bk*136+bn+5]=l;
                split2(v1.z, h, l); Bh[bk*136+bn+6]=h; Bl[bk*136+bn+6]=l;
                split2(v1.w, h, l); Bh[bk*136+bn+7]=h; Bl[bk*136+bn+7]=l;
            }
            __syncthreads();
#pragma unroll
            for (int k8 = 0; k8 < 16; k8 += 8) {
                int kk = k8 + (lane & 3);
                unsigned afh[2][4], afl[2][4], bfh[4][2], bfl[4][2];
#pragma unroll
                for (int tm = 0; tm < 2; tm++) {
                    int r = wm + tm*16 + (lane >> 2);
                    afh[tm][0] = __float_as_uint(Ah[r*20 + kk]);
                    afh[tm][1] = __float_as_uint(Ah[(r+8)*20 + kk]);
                    afh[tm][2] = __float_as_uint(Ah[r*20 + kk + 4]);
                    afh[tm][3] = __float_as_uint(Ah[(r+8)*20 + kk + 4]);
                    afl[tm][0] = __float_as_uint(Al[r*20 + kk]);
                    afl[tm][1] = __float_as_uint(Al[(r+8)*20 + kk]);
                    afl[tm][2] = __float_as_uint(Al[r*20 + kk + 4]);
                    afl[tm][3] = __float_as_uint(Al[(r+8)*20 + kk + 4]);
                }
#pragma unroll
                for (int tn = 0; tn < 4; tn++) {
                    int cn = wn + tn*8 + (lane >> 2);
                    bfh[tn][0] = __float_as_uint(Bh[kk*136 + cn]);
                    bfh[tn][1] = __float_as_uint(Bh[(kk+4)*136 + cn]);
                    bfl[tn][0] = __float_as_uint(Bl[kk*136 + cn]);
                    bfl[tn][1] = __float_as_uint(Bl[(kk+4)*136 + cn]);
                }
#pragma unroll
                for (int tm = 0; tm < 2; tm++)
#pragma unroll
                    for (int tn = 0; tn < 4; tn++) {
                        mma8(acc[tm][tn], afl[tm], bfh[tn]);
                        mma8(acc[tm][tn], afh[tm], bfl[tn]);
                        mma8(acc[tm][tn], afh[tm], bfh[tn]);
                    }
            }
            __syncthreads();
        }
    }
    float* out = &g_Gp[((size_t)(z*NH + c)*LP + i0)*Dm];
#pragma unroll
    for (int tm = 0; tm < 2; tm++)
#pragma unroll
        for (int tn = 0; tn < 4; tn++) {
            int r  = wm + tm*16 + (lane >> 2);
            int cn = wn + tn*8 + 2*(lane & 3);
            *(float2*)&out[(size_t)r*Dm + cn]     = make_float2(acc[tm][tn][0], acc[tm][tn][1]);
            *(float2*)&out[(size_t)(r+8)*Dm + cn] = make_float2(acc[tm][tn][2], acc[tm][tn][3]);
        }
}

// =============== Hm (3xTF32): C[j 64 x b 128] = Hsel^T @ U, tile 64x128, warps 2x4 ===============
__global__ __launch_bounds__(256) void gemm_hm_kernel() {
    int c = blockIdx.x, j0 = blockIdx.y * 64, z = blockIdx.z;
    const float* Hmp = g_Hmat + (size_t)(z*NH + c) * (LP*LP);
    __shared__ float Ah[16*72], Al[16*72];
    __shared__ float Bh[16*136], Bl[16*136];
    int t = threadIdx.x, lane = t & 31, warp = t >> 5;
    int wm = (warp >> 2) * 32, wn = (warp & 3) * 32;
    int ir = t >> 4, jq = (t & 15) << 2;
    int bk = t >> 4, bn = (t & 15) << 3;
    float acc[2][4][4] = {};
    for (int ss = 0; ss < 28; ss++) {
        int i0s = ss << 4;
        int mode = (i0s + 16 <= j0) ? 0 : ((i0s >= j0 + 64) ? 1 : 2);
        int npass = (mode == 2) ? 2 : 1;
        float4 hv = *(const float4*)&Hmp[(size_t)(i0s + ir)*LP + j0 + jq];
        float h4[4] = {hv.x, hv.y, hv.z, hv.w};
        for (int p = 0; p < npass; p++) {
            int g = (mode == 2) ? p : mode;
            int ig = i0s + ir;
#pragma unroll
            for (int q = 0; q < 4; q++) {
                float val = h4[q];
                if (mode == 2) {
                    int jg = j0 + jq + q;
                    bool keep = (g == 0) ? (ig < jg) : (ig > jg);
                    if (!keep) val = 0.f;
                }
                float h, l;
                split2(val, h, l);
                Ah[ir*72 + jq + q] = h;
                Al[ir*72 + jq + q] = l;
            }
            const float* Up = g_U + (size_t)(z*2 + g)*(LP*NH*Dm)
                             + (size_t)(i0s + bk)*1024 + c*Dm + bn;
            float4 u0 = *(const float4*)&Up[0];
            float4 u1 = *(const float4*)&Up[4];
            {
                float h, l;
                split2(u0.x, h, l); Bh[bk*136+bn+0]=h; Bl[bk*136+bn+0]=l;
                split2(u0.y, h, l); Bh[bk*136+bn+1]=h; Bl[bk*136+bn+1]=l;
                split2(u0.z, h, l); Bh[bk*136+bn+2]=h; Bl[bk*136+bn+2]=l;
                split2(u0.w, h, l); Bh[bk*136+bn+3]=h; Bl[bk*136+bn+3]=l;
                split2(u1.x, h, l); Bh[bk*136+bn+4]=h; Bl[bk*136+bn+4]=l;
                split2(u1.y, h, l); Bh[bk*136+bn+5]=h; Bl[bk*136+bn+5]=l;
                split2(u1.z, h, l); Bh[bk*136+bn+6]=h; Bl[bk*136+bn+6]=l;
                split2(u1.w, h, l); Bh[bk*136+bn+7]=h; Bl[bk*136+bn+7]=l;
            }
            __syncthreads();
#pragma unroll
            for (int k8 = 0; k8 < 16; k8 += 8) {
                int kk = k8 + (lane & 3);
                unsigned afh[2][4], afl[2][4], bfh[4][2], bfl[4][2];
#pragma unroll
                for (int tm = 0; tm < 2; tm++) {
                    int m = wm + tm*16 + (lane >> 2);
                    afh[tm][0] = __float_as_uint(Ah[kk*72 + m]);
                    afh[tm][1] = __float_as_uint(Ah[kk*72 + m + 8]);
                    afh[tm][2] = __float_as_uint(Ah[(kk+4)*72 + m]);
                    afh[tm][3] = __float_as_uint(Ah[(kk+4)*72 + m + 8]);
                    afl[tm][0] = __float_as_uint(Al[kk*72 + m]);
                    afl[tm][1] = __float_as_uint(Al[kk*72 + m + 8]);
                    afl[tm][2] = __float_as_uint(Al[(kk+4)*72 + m]);
                    afl[tm][3] = __float_as_uint(Al[(kk+4)*72 + m + 8]);
                }
#pragma unroll
                for (int tn = 0; tn < 4; tn++) {
                    int cn = wn + tn*8 + (lane >> 2);
                    bfh[tn][0] = __float_as_uint(Bh[kk*136 + cn]);
                    bfh[tn][1] = __float_as_uint(Bh[(kk+4)*136 + cn]);
                    bfl[tn][0] = __float_as_uint(Bl[kk*136 + cn]);
                    bfl[tn][1] = __float_as_uint(Bl[(kk+4)*136 + cn]);
                }
#pragma unroll
                for (int tm = 0; tm < 2; tm++)
#pragma unroll
                    for (int tn = 0; tn < 4; tn++) {
                        mma8(acc[tm][tn], afl[tm], bfh[tn]);
                        mma8(acc[tm][tn], afh[tm], bfl[tn]);
                        mma8(acc[tm][tn], afh[tm], bfh[tn]);
                    }
            }
            __syncthreads();
        }
    }
    float* out = &g_Hp[((size_t)(z*NH + c)*LP + j0)*Dm];
#pragma unroll
    for (int tm = 0; tm < 2; tm++)
#pragma unroll
        for (int tn = 0; tn < 4; tn++) {
            int r  = wm + tm*16 + (lane >> 2);
            int cn = wn + tn*8 + 2*(lane & 3);
            *(float2*)&out[(size_t)r*Dm + cn]     = make_float2(acc[tm][tn][0], acc[tm][tn][1]);
            *(float2*)&out[(size_t)(r+8)*Dm + cn] = make_float2(acc[tm][tn][2], acc[tm][tn][3]);
        }
}

// ---------------- q_z = (unary + sum_c Gp + sum_c Hp) * m1 ----------------
__global__ void reduce_qz_kernel() {
    int idx = blockIdx.x * blockDim.x + threadIdx.x;
    if (idx >= Bz*LP*Dm) return;
    int d = idx & 127;
    int zi = idx >> 7;
    int i = zi % LP, z = zi / LP;
    float s = g_unary[idx];
#pragma unroll
    for (int c = 0; c < NH; c++) {
        size_t o = ((size_t)(z*NH + c)*LP + i)*Dm + d;
        s += g_Gp[o] + g_Hp[o];
    }
    g_qz[idx] = s * g_m1[zi];
}

__global__ void out_kernel(float* __restrict__ out) {
    int idx = blockIdx.x * blockDim.x + threadIdx.x;
    if (idx >= Bz*L0c*Dm) return;
    int d = idx & 127;
    int zt = idx >> 7;
    int tt = zt % L0c, z = zt / L0c;
    out[idx] = g_qz[(z*LP + 1 + tt)*Dm + d];
}

extern "C" void kernel_launch(void* const* d_in, const int* in_sizes, int n_in,
                              void* d_out, int out_size) {
    const float* x = nullptr;
    const float* mask = nullptr;
    const float* tern = nullptr;
    for (int i = 0; i < n_in; i++) {
        if (in_sizes[i] == Bz*L0c*Dm)       x    = (const float*)d_in[i];
        else if (in_sizes[i] == Bz*L0c)     mask = (const float*)d_in[i];
        else if (in_sizes[i] == 2*Dm*Dm*NH) tern = (const float*)d_in[i];
    }
    if (!x || !mask || !tern) return;

    prep_unary_kernel<<<(Bz*LP*Dm + 255)/256, 256>>>(x, mask);
    zero_ppad_kernel<<<(128*Dm + 255)/256, 256>>>();
    prep_T_kernel<<<(2*Dm*Dm*NH + 255)/256, 256>>>(tern);

    for (int it = 0; it < NIT; it++) {
        softmax_p_kernel<<<Bz*Lr, 128>>>();
        gemm_uv_kernel<<<dim3(8, 7, 32), 256>>>();
        gemm_f_kernel<<<dim3(7, 28, Bz), 256>>>();
        hsoftmax_kernel<<<Bz*NH*Lr, 128>>>();
        gemm_g_kernel<<<dim3(NH, 7, Bz), 256>>>();
        gemm_hm_kernel<<<dim3(NH, 7, Bz), 256>>>();
        reduce_qz_kernel<<<(Bz*LP*Dm + 255)/256, 256>>>();
    }
    out_kernel<<<(Bz*L0c*Dm + 255)/256, 256>>>((float*)d_out);
}

// round 10
// speedup vs baseline: 1.1155x; 1.1155x over previous
#include <cuda_runtime.h>
#include <cstdint>

#define Bz 8
#define L0c 384
#define Lr 385
#define LP 448
#define Dm 128
#define NH 8
#define NIT 4
#define SA 72
#define SB 264

// ---------------- scratch ----------------
__device__ float g_unary[Bz*LP*Dm];
__device__ float g_qz[Bz*LP*Dm];
__device__ float g_m1[Bz*LP];
__device__ float g_P2[((size_t)Bz*LP + 128)*256];        // (hi,lo) interleaved over d
__device__ float g_T2u[(size_t)2*Dm*2048];               // [kg][a][2*(c*128+b)]
__device__ float g_T2v[(size_t)2*Dm*2048];               // [kg][b][2*(c*128+a)]
__device__ float g_U2[(size_t)Bz*2*LP*2048];             // [z][g][i][2*(c,b)]
__device__ float g_V2[(size_t)Bz*2*LP*2048];             // [z][g][j][2*(c,a)]
__device__ float g_Hmat[(size_t)Bz*NH*LP*LP];            // fp32 F then H
__device__ float g_Gp[(size_t)Bz*NH*LP*Dm];
__device__ float g_Hp[(size_t)Bz*NH*LP*Dm];

// ---------------- tf32 helpers ----------------
__device__ __forceinline__ float tf32r(float x) {
    unsigned u;
    asm("cvt.rna.tf32.f32 %0, %1;" : "=r"(u) : "f"(x));
    return __uint_as_float(u);
}
__device__ __forceinline__ void split2t(float x, float& h, float& l) {
    h = tf32r(x);
    l = tf32r(x - h);
}
__device__ __forceinline__ void mma8(float* c, const unsigned* a, const unsigned* b) {
    asm volatile(
        "mma.sync.aligned.m16n8k8.row.col.f32.tf32.tf32.f32 "
        "{%0,%1,%2,%3}, {%4,%5,%6,%7}, {%8,%9}, {%0,%1,%2,%3};"
        : "+f"(c[0]), "+f"(c[1]), "+f"(c[2]), "+f"(c[3])
        : "r"(a[0]), "r"(a[1]), "r"(a[2]), "r"(a[3]), "r"(b[0]), "r"(b[1]));
}
#define U32(x) __float_as_uint(x)

// ---------------- prep ----------------
__global__ void prep_unary_kernel(const float* __restrict__ x,
                                  const float* __restrict__ mask) {
    int idx = blockIdx.x * blockDim.x + threadIdx.x;
    if (idx >= Bz*LP*Dm) return;
    int d = idx & 127;
    int zi = idx >> 7;
    int i = zi % LP, z = zi / LP;
    float v = 0.f;
    if (i >= 1 && i < Lr) v = x[(z*L0c + (i-1))*Dm + d];
    float m = (i == 0) ? 1.f : ((i < Lr) ? mask[z*L0c + (i-1)] : 0.f);
    g_unary[idx] = v;
    g_qz[idx]    = v * m;
    if (d == 0) g_m1[zi] = m;
}

__global__ void zero_p2_kernel() {
    size_t n = ((size_t)Bz*LP + 128)*256;
    size_t idx = (size_t)blockIdx.x * blockDim.x + threadIdx.x;
    if (idx < n) g_P2[idx] = 0.f;
}

__global__ void prep_T_kernel(const float* __restrict__ tern) {
    int idx = blockIdx.x * blockDim.x + threadIdx.x;
    if (idx >= 2*Dm*Dm*NH) return;
    int c = idx & 7;
    int r = idx >> 3;
    int b = r & 127; r >>= 7;
    int a = r & 127;
    int k = r >> 7;
    float v = tern[idx];
    float h, l; split2t(v, h, l);
    size_t ou = ((size_t)(k*Dm + a))*2048 + 2*((c<<7) + b);
    g_T2u[ou] = h; g_T2u[ou+1] = l;
    size_t ov = ((size_t)(k*Dm + b))*2048 + 2*((c<<7) + a);
    g_T2v[ov] = h; g_T2v[ov+1] = l;
}

// ---------------- softmax over d -> P2 (split planes) ----------------
__global__ void softmax_p_kernel() {
    int row = blockIdx.x;
    int z = row / Lr, i = row - z*Lr;
    const float* src = g_qz + (z*LP + i)*Dm;
    int t = threadIdx.x;
    float v = src[t];
    __shared__ float shm[4], shs[4];
    float m = v;
#pragma unroll
    for (int o = 16; o; o >>= 1) m = fmaxf(m, __shfl_xor_sync(0xffffffffu, m, o));
    if ((t & 31) == 0) shm[t >> 5] = m;
    __syncthreads();
    m = fmaxf(fmaxf(shm[0], shm[1]), fmaxf(shm[2], shm[3]));
    float e = __expf(v - m);
    float s = e;
#pragma unroll
    for (int o = 16; o; o >>= 1) s += __shfl_xor_sync(0xffffffffu, s, o);
    if ((t & 31) == 0) shs[t >> 5] = s;
    __syncthreads();
    s = (shs[0] + shs[1]) + (shs[2] + shs[3]);
    float pv = e / s * g_m1[z*LP + i];
    float h, l; split2t(pv, h, l);
    float2 w; w.x = h; w.y = l;
    *(float2*)&g_P2[((size_t)(z*LP + i))*256 + 2*t] = w;
}

// =============== UV (3xTF32): C2[448x1024] = P2 @ T2, tile 64x128, warps 2x4 ===============
__global__ __launch_bounds__(256) void gemm_uv_kernel() {
    extern __shared__ float sm[];
    float* As = sm;            // 64 x SA
    float* Bs = sm + 64*SA;    // 32 x SB
    int inst = blockIdx.z;
    int uv = inst & 1, kg = (inst >> 1) & 1, z = inst >> 2;
    const float* A2 = g_P2 + (size_t)(z*LP)*256;
    const float* B2 = (uv ? g_T2v : g_T2u) + (size_t)kg*Dm*2048;
    float*       C2 = (uv ? g_V2 : g_U2) + (size_t)(z*2 + kg)*LP*2048;
    int m0 = blockIdx.y*64, n0 = blockIdx.x*128;
    int t = threadIdx.x, lane = t & 31, warp = t >> 5;
    int wm = (warp >> 2)*32, wn = (warp & 3)*32;
    float acc[2][4][4] = {};
    for (int s = 0; s < 4; s++) {
        int k0 = s*32;
        for (int f = t; f < 1024; f += 256) {
            int row = f >> 4, q = f & 15;
            *(float4*)&As[row*SA + q*4] =
                *(const float4*)&A2[(size_t)(m0+row)*256 + 2*k0 + q*4];
        }
        for (int f = t; f < 2048; f += 256) {
            int row = f >> 6, q = f & 63;
            *(float4*)&Bs[row*SB + q*4] =
                *(const float4*)&B2[(size_t)(k0+row)*2048 + 2*n0 + q*4];
        }
        __syncthreads();
#pragma unroll
        for (int k8 = 0; k8 < 32; k8 += 8) {
            int kk = k8 + (lane & 3);
            unsigned afh[2][4], afl[2][4], bfh[4][2], bfl[4][2];
#pragma unroll
            for (int tm = 0; tm < 2; tm++) {
                int r = wm + tm*16 + (lane >> 2);
                float2 p0 = *(float2*)&As[r*SA + 2*kk];
                float2 p1 = *(float2*)&As[(r+8)*SA + 2*kk];
                float2 p2 = *(float2*)&As[r*SA + 2*kk + 8];
                float2 p3 = *(float2*)&As[(r+8)*SA + 2*kk + 8];
                afh[tm][0]=U32(p0.x); afh[tm][1]=U32(p1.x); afh[tm][2]=U32(p2.x); afh[tm][3]=U32(p3.x);
                afl[tm][0]=U32(p0.y); afl[tm][1]=U32(p1.y); afl[tm][2]=U32(p2.y); afl[tm][3]=U32(p3.y);
            }
#pragma unroll
            for (int tn = 0; tn < 4; tn++) {
                int cn = wn + tn*8 + (lane >> 2);
                float2 q0 = *(float2*)&Bs[kk*SB + 2*cn];
                float2 q1 = *(float2*)&Bs[(kk+4)*SB + 2*cn];
                bfh[tn][0]=U32(q0.x); bfh[tn][1]=U32(q1.x);
                bfl[tn][0]=U32(q0.y); bfl[tn][1]=U32(q1.y);
            }
#pragma unroll
            for (int tm = 0; tm < 2; tm++)
#pragma unroll
                for (int tn = 0; tn < 4; tn++) {
                    mma8(acc[tm][tn], afl[tm], bfh[tn]);
                    mma8(acc[tm][tn], afh[tm], bfl[tn]);
                    mma8(acc[tm][tn], afh[tm], bfh[tn]);
                }
        }
        __syncthreads();
    }
#pragma unroll
    for (int tm = 0; tm < 2; tm++)
#pragma unroll
        for (int tn = 0; tn < 4; tn++) {
            int r  = m0 + wm + tm*16 + (lane >> 2);
            int cb = n0 + wn + tn*8 + 2*(lane & 3);
            float h0,l0,h1,l1;
            split2t(acc[tm][tn][0], h0, l0);
            split2t(acc[tm][tn][1], h1, l1);
            float4 w0; w0.x=h0; w0.y=l0; w0.z=h1; w0.w=l1;
            *(float4*)&C2[(size_t)r*2048 + 2*cb] = w0;
            split2t(acc[tm][tn][2], h0, l0);
            split2t(acc[tm][tn][3], h1, l1);
            float4 w1; w1.x=h0; w1.y=l0; w1.z=h1; w1.w=l1;
            *(float4*)&C2[(size_t)(r+8)*2048 + 2*cb] = w1;
        }
}

// =============== F (3xTF32): Hmat[m=3584 x j] = U2[m][b].P2[j][b] NT, tile 128x64, warps 4x2 ===============
__global__ __launch_bounds__(256) void gemm_f_kernel() {
    extern __shared__ float sm[];
    float* As = sm;              // 128 x SA
    float* Ps = sm + 128*SA;     // 64 x SA
    int z = blockIdx.z;
    int m0 = blockIdx.y*128, j0 = blockIdx.x*64;
    int ilo = m0 >> 3;
    int mode = (j0 >= ilo + 16) ? 0 : ((j0 + 64 <= ilo) ? 1 : 2);
    int npass = (mode == 2) ? 2 : 1;
    int t = threadIdx.x, lane = t & 31, warp = t >> 5;
    int wm = (warp >> 1)*32, wn = (warp & 1)*32;
    for (int p = 0; p < npass; p++) {
        int g = (mode == 2) ? p : mode;
        const float* A2 = g_U2 + (size_t)(z*2 + g)*LP*2048;   // flat stacked row m -> m*256
        float acc[2][4][4] = {};
        for (int s = 0; s < 4; s++) {
            int k0 = s*32;
            for (int f = t; f < 2048; f += 256) {
                int row = f >> 4, q = f & 15;
                *(float4*)&As[row*SA + q*4] =
                    *(const float4*)&A2[(size_t)(m0+row)*256 + 2*k0 + q*4];
            }
            for (int f = t; f < 1024; f += 256) {
                int row = f >> 4, q = f & 15;
                *(float4*)&Ps[row*SA + q*4] =
                    *(const float4*)&g_P2[((size_t)(z*LP + j0 + row))*256 + 2*k0 + q*4];
            }
            __syncthreads();
#pragma unroll
            for (int k8 = 0; k8 < 32; k8 += 8) {
                int kk = k8 + (lane & 3);
                unsigned afh[2][4], afl[2][4], bfh[4][2], bfl[4][2];
#pragma unroll
                for (int tm = 0; tm < 2; tm++) {
                    int r = wm + tm*16 + (lane >> 2);
                    float2 p0 = *(float2*)&As[r*SA + 2*kk];
                    float2 p1 = *(float2*)&As[(r+8)*SA + 2*kk];
                    float2 p2 = *(float2*)&As[r*SA + 2*kk + 8];
                    float2 p3 = *(float2*)&As[(r+8)*SA + 2*kk + 8];
                    afh[tm][0]=U32(p0.x); afh[tm][1]=U32(p1.x); afh[tm][2]=U32(p2.x); afh[tm][3]=U32(p3.x);
                    afl[tm][0]=U32(p0.y); afl[tm][1]=U32(p1.y); afl[tm][2]=U32(p2.y); afl[tm][3]=U32(p3.y);
                }
#pragma unroll
                for (int tn = 0; tn < 4; tn++) {
                    int cn = wn + tn*8 + (lane >> 2);
                    float2 q0 = *(float2*)&Ps[cn*SA + 2*kk];
                    float2 q1 = *(float2*)&Ps[cn*SA + 2*kk + 8];
                    bfh[tn][0]=U32(q0.x); bfh[tn][1]=U32(q1.x);
                    bfl[tn][0]=U32(q0.y); bfl[tn][1]=U32(q1.y);
                }
#pragma unroll
                for (int tm = 0; tm < 2; tm++)
#pragma unroll
                    for (int tn = 0; tn < 4; tn++) {
                        mma8(acc[tm][tn], afl[tm], bfh[tn]);
                        mma8(acc[tm][tn], afh[tm], bfl[tn]);
                        mma8(acc[tm][tn], afh[tm], bfh[tn]);
                    }
            }
            __syncthreads();
        }
#pragma unroll
        for (int tm = 0; tm < 2; tm++)
#pragma unroll
            for (int tn = 0; tn < 4; tn++) {
                int jc = j0 + wn + tn*8 + 2*(lane & 3);
#pragma unroll
                for (int half = 0; half < 2; half++) {
                    int m = m0 + wm + tm*16 + (lane >> 2) + half*8;
                    int i = m >> 3, cc = m & 7;
                    size_t off = ((size_t)(z*NH + cc)*LP + i)*LP + jc;
                    float v0 = acc[tm][tn][half*2], v1 = acc[tm][tn][half*2 + 1];
                    if (mode != 2) {
                        float2 w; w.x = v0; w.y = v1;
                        *(float2*)&g_Hmat[off] = w;
                    } else if (p == 0) {
                        float2 w;
                        w.x = (jc     > i) ? v0 : 0.f;
                        w.y = (jc + 1 > i) ? v1 : 0.f;
                        *(float2*)&g_Hmat[off] = w;
                    } else {
                        if (jc     < i) g_Hmat[off]     = v0;
                        if (jc + 1 < i) g_Hmat[off + 1] = v1;
                    }
                }
            }
    }
}

// ---------------- H softmax over j (fp32 in place) ----------------
__global__ void hsoftmax_kernel() {
    int bid = blockIdx.x;
    int i = bid % Lr;
    int zc = bid / Lr;
    int z = zc >> 3;
    float* row = g_Hmat + (size_t)zc * (LP*LP) + (size_t)i * LP;
    int t = threadIdx.x;
    if (i == 0) {
        for (int j = t; j < Lr; j += 128) row[j] = 0.f;
        return;
    }
    float mi = g_m1[z*LP + i];
    float lv[4];
    float mx = -3.4e38f;
#pragma unroll
    for (int r = 0; r < 4; r++) {
        int j = t + r*128;
        float l = -3.4e38f;
        if (j < Lr) {
            bool ok = (mi != 0.f) && (g_m1[z*LP + j] != 0.f) && (j != i);
            l = ok ? row[j] * 128.f : -1e9f;
        }
        lv[r] = l;
        mx = fmaxf(mx, l);
    }
    __shared__ float shm[4], shs[4];
#pragma unroll
    for (int o = 16; o; o >>= 1) mx = fmaxf(mx, __shfl_xor_sync(0xffffffffu, mx, o));
    if ((t & 31) == 0) shm[t >> 5] = mx;
    __syncthreads();
    mx = fmaxf(fmaxf(shm[0], shm[1]), fmaxf(shm[2], shm[3]));
    float ev[4];
    float s = 0.f;
#pragma unroll
    for (int r = 0; r < 4; r++) {
        int j = t + r*128;
        ev[r] = 0.f;
        if (j < Lr) { ev[r] = __expf(lv[r] - mx); s += ev[r]; }
    }
#pragma unroll
    for (int o = 16; o; o >>= 1) s += __shfl_xor_sync(0xffffffffu, s, o);
    if ((t & 31) == 0) shs[t >> 5] = s;
    __syncthreads();
    s = (shs[0] + shs[1]) + (shs[2] + shs[3]);
    float inv = 1.f / s;
#pragma unroll
    for (int r = 0; r < 4; r++) {
        int j = t + r*128;
        if (j < Lr) row[j] = ev[r] * inv;
    }
}

// =============== G (3xTF32): Gp[i x a128] = Hsel @ V2, tile 64x128, warps 2x4 ===============
__global__ __launch_bounds__(256) void gemm_g_kernel() {
    extern __shared__ float sm[];
    float* As = sm;           // 64 x SA  (H masked, split pairs)
    float* Bs = sm + 64*SA;   // 32 x SB
    int c = blockIdx.x, i0 = blockIdx.y*64, z = blockIdx.z;
    const float* Hmp = g_Hmat + (size_t)(z*NH + c)*(LP*LP);
    int t = threadIdx.x, lane = t & 31, warp = t >> 5;
    int wm = (warp >> 2)*32, wn = (warp & 3)*32;
    int ar = t >> 2, acol0 = (t & 3)*8;
    float acc[2][4][4] = {};
    for (int s = 0; s < 14; s++) {
        int j0s = s*32;
        int mode = (j0s >= i0 + 64) ? 0 : ((j0s + 32 <= i0) ? 1 : 2);
        int npass = (mode == 2) ? 2 : 1;
        for (int p = 0; p < npass; p++) {
            int g = (mode == 2) ? p : mode;
            int ig = i0 + ar;
#pragma unroll
            for (int q = 0; q < 8; q += 2) {
                float2 hv = *(const float2*)&Hmp[(size_t)ig*LP + j0s + acol0 + q];
                if (mode == 2) {
                    int jg = j0s + acol0 + q;
                    bool k0b = (g == 0) ? (jg     > ig) : (jg     < ig);
                    bool k1b = (g == 0) ? (jg + 1 > ig) : (jg + 1 < ig);
                    if (!k0b) hv.x = 0.f;
                    if (!k1b) hv.y = 0.f;
                }
                float h0,l0,h1,l1;
                split2t(hv.x, h0, l0);
                split2t(hv.y, h1, l1);
                float4 w; w.x=h0; w.y=l0; w.z=h1; w.w=l1;
                *(float4*)&As[ar*SA + 2*(acol0 + q)] = w;
            }
            const float* B2 = g_V2 + (size_t)(z*2 + g)*LP*2048 + (size_t)c*256;
            for (int f = t; f < 2048; f += 256) {
                int row = f >> 6, q = f & 63;
                *(float4*)&Bs[row*SB + q*4] =
                    *(const float4*)&B2[(size_t)(j0s + row)*2048 + q*4];
            }
            __syncthreads();
#pragma unroll
            for (int k8 = 0; k8 < 32; k8 += 8) {
                int kk = k8 + (lane & 3);
                unsigned afh[2][4], afl[2][4], bfh[4][2], bfl[4][2];
#pragma unroll
                for (int tm = 0; tm < 2; tm++) {
                    int r = wm + tm*16 + (lane >> 2);
                    float2 p0 = *(float2*)&As[r*SA + 2*kk];
                    float2 p1 = *(float2*)&As[(r+8)*SA + 2*kk];
                    float2 p2 = *(float2*)&As[r*SA + 2*kk + 8];
                    float2 p3 = *(float2*)&As[(r+8)*SA + 2*kk + 8];
                    afh[tm][0]=U32(p0.x); afh[tm][1]=U32(p1.x); afh[tm][2]=U32(p2.x); afh[tm][3]=U32(p3.x);
                    afl[tm][0]=U32(p0.y); afl[tm][1]=U32(p1.y); afl[tm][2]=U32(p2.y); afl[tm][3]=U32(p3.y);
                }
#pragma unroll
                for (int tn = 0; tn < 4; tn++) {
                    int cn = wn + tn*8 + (lane >> 2);
                    float2 q0 = *(float2*)&Bs[kk*SB + 2*cn];
                    float2 q1 = *(float2*)&Bs[(kk+4)*SB + 2*cn];
                    bfh[tn][0]=U32(q0.x); bfh[tn][1]=U32(q1.x);
                    bfl[tn][0]=U32(q0.y); bfl[tn][1]=U32(q1.y);
                }
#pragma unroll
                for (int tm = 0; tm < 2; tm++)
#pragma unroll
                    for (int tn = 0; tn < 4; tn++) {
                        mma8(acc[tm][tn], afl[tm], bfh[tn]);
                        mma8(acc[tm][tn], afh[tm], bfl[tn]);
                        mma8(acc[tm][tn], afh[tm], bfh[tn]);
                    }
            }
            __syncthreads();
        }
    }
#pragma unroll
    for (int tm = 0; tm < 2; tm++)
#pragma unroll
        for (int tn = 0; tn < 4; tn++) {
            int r  = i0 + wm + tm*16 + (lane >> 2);
            int cn = wn + tn*8 + 2*(lane & 3);
            float2 w0; w0.x = acc[tm][tn][0]; w0.y = acc[tm][tn][1];
            float2 w1; w1.x = acc[tm][tn][2]; w1.y = acc[tm][tn][3];
            *(float2*)&g_Gp[((size_t)(z*NH + c)*LP + r)*Dm + cn]     = w0;
            *(float2*)&g_Gp[((size_t)(z*NH + c)*LP + r + 8)*Dm + cn] = w1;
        }
}

// =============== Hm (3xTF32): Hp[j x b128] = Hsel^T @ U2, tile 64x128, warps 2x4 ===============
__global__ __launch_bounds__(256) void gemm_hm_kernel() {
    extern __shared__ float sm[];
    float* As = sm;           // 64(j) x SA (k=i pairs)
    float* Bs = sm + 64*SA;   // 32 x SB
    int c = blockIdx.x, j0 = blockIdx.y*64, z = blockIdx.z;
    const float* Hmp = g_Hmat + (size_t)(z*NH + c)*(LP*LP);
    int t = threadIdx.x, lane = t & 31, warp = t >> 5;
    int wm = (warp >> 2)*32, wn = (warp & 3)*32;
    int air = t >> 3, aj0 = (t & 7)*8;
    float acc[2][4][4] = {};
    for (int s = 0; s < 14; s++) {
        int i0s = s*32;
        int mode = (i0s + 32 <= j0) ? 0 : ((i0s >= j0 + 64) ? 1 : 2);
        int npass = (mode == 2) ? 2 : 1;
        for (int p = 0; p < npass; p++) {
            int g = (mode == 2) ? p : mode;
            int ig = i0s + air;
#pragma unroll
            for (int q = 0; q < 8; q += 2) {
                float2 hv = *(const float2*)&Hmp[(size_t)ig*LP + j0 + aj0 + q];
                if (mode == 2) {
                    int jg = j0 + aj0 + q;
                    bool k0b = (g == 0) ? (ig < jg)     : (ig > jg);
                    bool k1b = (g == 0) ? (ig < jg + 1) : (ig > jg + 1);
                    if (!k0b) hv.x = 0.f;
                    if (!k1b) hv.y = 0.f;
                }
                float h0,l0,h1,l1;
                split2t(hv.x, h0, l0);
                split2t(hv.y, h1, l1);
                float2 w0; w0.x = h0; w0.y = l0;
                float2 w1; w1.x = h1; w1.y = l1;
                *(float2*)&As[(aj0 + q)*SA + 2*air]     = w0;
                *(float2*)&As[(aj0 + q + 1)*SA + 2*air] = w1;
            }
            const float* B2 = g_U2 + (size_t)(z*2 + g)*LP*2048 + (size_t)c*256;
            for (int f = t; f < 2048; f += 256) {
                int row = f >> 6, q = f & 63;
                *(float4*)&Bs[row*SB + q*4] =
                    *(const float4*)&B2[(size_t)(i0s + row)*2048 + q*4];
            }
            __syncthreads();
#pragma unroll
            for (int k8 = 0; k8 < 32; k8 += 8) {
                int kk = k8 + (lane & 3);
                unsigned afh[2][4], afl[2][4], bfh[4][2], bfl[4][2];
#pragma unroll
                for (int tm = 0; tm < 2; tm++) {
                    int r = wm + tm*16 + (lane >> 2);
                    float2 p0 = *(float2*)&As[r*SA + 2*kk];
                    float2 p1 = *(float2*)&As[(r+8)*SA + 2*kk];
                    float2 p2 = *(float2*)&As[r*SA + 2*kk + 8];
                    float2 p3 = *(float2*)&As[(r+8)*SA + 2*kk + 8];
                    afh[tm][0]=U32(p0.x); afh[tm][1]=U32(p1.x); afh[tm][2]=U32(p2.x); afh[tm][3]=U32(p3.x);
                    afl[tm][0]=U32(p0.y); afl[tm][1]=U32(p1.y); afl[tm][2]=U32(p2.y); afl[tm][3]=U32(p3.y);
                }
#pragma unroll
                for (int tn = 0; tn < 4; tn++) {
                    int cn = wn + tn*8 + (lane >> 2);
                    float2 q0 = *(float2*)&Bs[kk*SB + 2*cn];
                    float2 q1 = *(float2*)&Bs[(kk+4)*SB + 2*cn];
                    bfh[tn][0]=U32(q0.x); bfh[tn][1]=U32(q1.x);
                    bfl[tn][0]=U32(q0.y); bfl[tn][1]=U32(q1.y);
                }
#pragma unroll
                for (int tm = 0; tm < 2; tm++)
#pragma unroll
                    for (int tn = 0; tn < 4; tn++) {
                        mma8(acc[tm][tn], afl[tm], bfh[tn]);
                        mma8(acc[tm][tn], afh[tm], bfl[tn]);
                        mma8(acc[tm][tn], afh[tm], bfh[tn]);
                    }
            }
            __syncthreads();
        }
    }
#pragma unroll
    for (int tm = 0; tm < 2; tm++)
#pragma unroll
        for (int tn = 0; tn < 4; tn++) {
            int r  = j0 + wm + tm*16 + (lane >> 2);
            int cn = wn + tn*8 + 2*(lane & 3);
            float2 w0; w0.x = acc[tm][tn][0]; w0.y = acc[tm][tn][1];
            float2 w1; w1.x = acc[tm][tn][2]; w1.y = acc[tm][tn][3];
            *(float2*)&g_Hp[((size_t)(z*NH + c)*LP + r)*Dm + cn]     = w0;
            *(float2*)&g_Hp[((size_t)(z*NH + c)*LP + r + 8)*Dm + cn] = w1;
        }
}

// ---------------- q_z = (unary + sum_c Gp + sum_c Hp) * m1 ----------------
__global__ void reduce_qz_kernel() {
    int idx = blockIdx.x * blockDim.x + threadIdx.x;
    if (idx >= Bz*LP*Dm) return;
    int d = idx & 127;
    int zi = idx >> 7;
    int i = zi % LP, z = zi / LP;
    float s = g_unary[idx];
#pragma unroll
    for (int c = 0; c < NH; c++) {
        size_t o = ((size_t)(z*NH + c)*LP + i)*Dm + d;
        s += g_Gp[o] + g_Hp[o];
    }
    g_qz[idx] = s * g_m1[zi];
}

__global__ void out_kernel(float* __restrict__ out) {
    int idx = blockIdx.x * blockDim.x + threadIdx.x;
    if (idx >= Bz*L0c*Dm) return;
    int d = idx & 127;
    int zt = idx >> 7;
    int tt = zt % L0c, z = zt / L0c;
    out[idx] = g_qz[(z*LP + 1 + tt)*Dm + d];
}

extern "C" void kernel_launch(void* const* d_in, const int* in_sizes, int n_in,
                              void* d_out, int out_size) {
    const float* x = nullptr;
    const float* mask = nullptr;
    const float* tern = nullptr;
    for (int i = 0; i < n_in; i++) {
        if (in_sizes[i] == Bz*L0c*Dm)       x    = (const float*)d_in[i];
        else if (in_sizes[i] == Bz*L0c)     mask = (const float*)d_in[i];
        else if (in_sizes[i] == 2*Dm*Dm*NH) tern = (const float*)d_in[i];
    }
    if (!x || !mask || !tern) return;

    const int UV_SMEM = (64*SA + 32*SB)*4;   // 52224
    const int F_SMEM  = (128*SA + 64*SA)*4;  // 55296
    const int GH_SMEM = (64*SA + 32*SB)*4;   // 52224
    static bool attrs_set = false;
    if (!attrs_set) {
        cudaFuncSetAttribute(gemm_uv_kernel, cudaFuncAttributeMaxDynamicSharedMemorySize, UV_SMEM);
        cudaFuncSetAttribute(gemm_f_kernel,  cudaFuncAttributeMaxDynamicSharedMemorySize, F_SMEM);
        cudaFuncSetAttribute(gemm_g_kernel,  cudaFuncAttributeMaxDynamicSharedMemorySize, GH_SMEM);
        cudaFuncSetAttribute(gemm_hm_kernel, cudaFuncAttributeMaxDynamicSharedMemorySize, GH_SMEM);
        attrs_set = true;
    }

    prep_unary_kernel<<<(Bz*LP*Dm + 255)/256, 256>>>(x, mask);
    zero_p2_kernel<<<(int)((((size_t)Bz*LP + 128)*256 + 255)/256), 256>>>();
    prep_T_kernel<<<(2*Dm*Dm*NH + 255)/256, 256>>>(tern);

    for (int it = 0; it < NIT; it++) {
        softmax_p_kernel<<<Bz*Lr, 128>>>();
        gemm_uv_kernel<<<dim3(8, 7, 32), 256, UV_SMEM>>>();
        gemm_f_kernel<<<dim3(7, 28, Bz), 256, F_SMEM>>>();
        hsoftmax_kernel<<<Bz*NH*Lr, 128>>>();
        gemm_g_kernel<<<dim3(NH, 7, Bz), 256, GH_SMEM>>>();
        gemm_hm_kernel<<<dim3(NH, 7, Bz), 256, GH_SMEM>>>();
        reduce_qz_kernel<<<(Bz*LP*Dm + 255)/256, 256>>>();
    }
    out_kernel<<<(Bz*L0c*Dm + 255)/256, 256>>>((float*)d_out);
}

// round 12
// speedup vs baseline: 1.6829x; 1.5086x over previous
#include <cuda_runtime.h>
#include <cuda_fp16.h>
#include <cstdint>

#define Bz 8
#define L0c 384
#define Lr 385
#define LP 448
#define Dm 128
#define NH 8
#define NIT 4

// ---------------- scratch (all fp32, R2 layouts) ----------------
__device__ float g_unary[Bz*LP*Dm];
__device__ float g_qz[Bz*LP*Dm];
__device__ float g_P[(Bz*LP + 128)*Dm];
__device__ float g_m1[Bz*LP];
__device__ float g_Tu[2*Dm*NH*Dm];        // [k][a][c][b]
__device__ float g_Tv[2*Dm*NH*Dm];        // [k][b][c][a]
__device__ float g_U[Bz*2*LP*NH*Dm];      // [z][g][i][(c,b)] == stacked m=(i*8+c)
__device__ float g_V[Bz*2*LP*NH*Dm];      // [z][g][j][(c,a)]
__device__ float g_Hmat[(size_t)Bz*NH*LP*LP];
__device__ float g_Gp[Bz*NH*LP*Dm];
__device__ float g_Hp[Bz*NH*LP*Dm];

// ---------------- fp16 split helpers ----------------
__device__ __forceinline__ void split2h(float x, __half& h, __half& l) {
    h = __float2half_rn(x);
    l = __float2half_rn(x - __half2float(h));
}
__device__ __forceinline__ void mmah(float* c, const unsigned* a, const unsigned* b) {
    asm volatile(
        "mma.sync.aligned.m16n8k16.row.col.f32.f16.f16.f32 "
        "{%0,%1,%2,%3}, {%4,%5,%6,%7}, {%8,%9}, {%0,%1,%2,%3};"
        : "+f"(c[0]), "+f"(c[1]), "+f"(c[2]), "+f"(c[3])
        : "r"(a[0]), "r"(a[1]), "r"(a[2]), "r"(a[3]), "r"(b[0]), "r"(b[1]));
}
__device__ __forceinline__ __half2 mkh2(__half a, __half b) { __half2 r; r.x = a; r.y = b; return r; }
#define LDU2(p) (*(const unsigned*)(p))

// ---------------- prep ----------------
__global__ void prep_unary_kernel(const float* __restrict__ x,
                                  const float* __restrict__ mask) {
    int idx = blockIdx.x * blockDim.x + threadIdx.x;
    if (idx >= Bz*LP*Dm) return;
    int d = idx & 127;
    int zi = idx >> 7;
    int i = zi % LP, z = zi / LP;
    float v = 0.f;
    if (i >= 1 && i < Lr) v = x[(z*L0c + (i-1))*Dm + d];
    float m = (i == 0) ? 1.f : ((i < Lr) ? mask[z*L0c + (i-1)] : 0.f);
    g_unary[idx] = v;
    g_qz[idx]    = v * m;
    g_P[idx]     = 0.f;
    if (d == 0) g_m1[zi] = m;
}

__global__ void zero_ppad_kernel() {
    int idx = blockIdx.x * blockDim.x + threadIdx.x;
    if (idx < 128*Dm) g_P[Bz*LP*Dm + idx] = 0.f;
}

__global__ void prep_T_kernel(const float* __restrict__ tern) {
    int idx = blockIdx.x * blockDim.x + threadIdx.x;
    if (idx >= 2*Dm*Dm*NH) return;
    int c = idx & 7;
    int r = idx >> 3;
    int b = r & 127; r >>= 7;
    int a = r & 127;
    int k = r >> 7;
    float v = tern[idx];
    g_Tu[((k*Dm + a)*NH + c)*Dm + b] = v;
    g_Tv[((k*Dm + b)*NH + c)*Dm + a] = v;
}

// ---------------- softmax over d ----------------
__global__ void softmax_p_kernel() {
    int row = blockIdx.x;
    int z = row / Lr, i = row - z*Lr;
    const float* src = g_qz + (z*LP + i)*Dm;
    int t = threadIdx.x;
    float v = src[t];
    __shared__ float shm[4], shs[4];
    float m = v;
#pragma unroll
    for (int o = 16; o; o >>= 1) m = fmaxf(m, __shfl_xor_sync(0xffffffffu, m, o));
    if ((t & 31) == 0) shm[t >> 5] = m;
    __syncthreads();
    m = fmaxf(fmaxf(shm[0], shm[1]), fmaxf(shm[2], shm[3]));
    float e = __expf(v - m);
    float s = e;
#pragma unroll
    for (int o = 16; o; o >>= 1) s += __shfl_xor_sync(0xffffffffu, s, o);
    if ((t & 31) == 0) shs[t >> 5] = s;
    __syncthreads();
    s = (shs[0] + shs[1]) + (shs[2] + shs[3]);
    g_P[(z*LP + i)*Dm + t] = e / s * g_m1[z*LP + i];
}

// =============== UV (R2 FFMA, proven): C[448x1024] = P @ T, tile 64x128 ===============
__global__ __launch_bounds__(256) void gemm_uv_kernel() {
    int inst = blockIdx.z;
    int uv = inst & 1, kg = (inst >> 1) & 1, z = inst >> 2;
    const float* A  = g_P + (size_t)(z*LP)*Dm;
    const float* Bm = (uv ? g_Tv : g_Tu) + kg * (Dm*NH*Dm);
    float*       C  = (uv ? g_V : g_U) + (size_t)(z*2 + kg) * (LP*NH*Dm);
    int m0 = blockIdx.y * 64, n0 = blockIdx.x * 128;
    __shared__ float As[16][68];
    __shared__ float Bs[16][128];
    int t = threadIdx.x, ty = t >> 4, tx = t & 15;
    int arow = t >> 2, acol = (t & 3) << 2;
    int brow = t >> 4, bcol = (t & 15) << 3;
    float4 pa, pb0, pb1;
    pa  = *(const float4*)&A[(m0 + arow)*Dm + acol];
    pb0 = *(const float4*)&Bm[brow*1024 + n0 + bcol];
    pb1 = *(const float4*)&Bm[brow*1024 + n0 + bcol + 4];
    float acc[4][8] = {};
    for (int s = 0; s < 8; s++) {
        As[acol+0][arow]=pa.x; As[acol+1][arow]=pa.y; As[acol+2][arow]=pa.z; As[acol+3][arow]=pa.w;
        *(float4*)&Bs[brow][bcol]   = pb0;
        *(float4*)&Bs[brow][bcol+4] = pb1;
        __syncthreads();
        if (s < 7) {
            int kt = (s+1) << 4;
            pa  = *(const float4*)&A[(m0 + arow)*Dm + kt + acol];
            pb0 = *(const float4*)&Bm[(kt+brow)*1024 + n0 + bcol];
            pb1 = *(const float4*)&Bm[(kt+brow)*1024 + n0 + bcol + 4];
        }
#pragma unroll
        for (int kk = 0; kk < 16; kk++) {
            float a[4], b[8];
            *(float4*)a     = *(const float4*)&As[kk][ty << 2];
            *(float4*)b     = *(const float4*)&Bs[kk][tx << 2];
            *(float4*)(b+4) = *(const float4*)&Bs[kk][64 + (tx << 2)];
#pragma unroll
            for (int u = 0; u < 4; u++)
#pragma unroll
                for (int v = 0; v < 8; v++) acc[u][v] = fmaf(a[u], b[v], acc[u][v]);
        }
        __syncthreads();
    }
#pragma unroll
    for (int u = 0; u < 4; u++) {
        size_t ro = (size_t)(m0 + (ty<<2) + u)*1024 + n0;
        *(float4*)&C[ro + (tx<<2)]      = *(float4*)&acc[u][0];
        *(float4*)&C[ro + 64 + (tx<<2)] = *(float4*)&acc[u][4];
    }
}

// =============== F (fp16 3-term): C[m=3584 x j] = U[m][b].P[j][b] NT, tile 128x64, warps 4x2 ===============
__global__ __launch_bounds__(256) void gemm_f_kernel() {
    __shared__ __half2 Ah2[8*136], Al2[8*136];   // [kpair][m]
    __shared__ __half2 Bh2[8*72],  Bl2[8*72];    // [kpair][j]
    int z = blockIdx.z;
    int m0 = blockIdx.y*128, j0 = blockIdx.x*64;
    int ilo = m0 >> 3;
    int mode = (j0 >= ilo + 16) ? 0 : ((j0 + 64 <= ilo) ? 1 : 2);
    int npass = (mode == 2) ? 2 : 1;
    int t = threadIdx.x, lane = t & 31, warp = t >> 5;
    int wm = (warp >> 1)*32, wn = (warp & 1)*32;
    int gr = lane >> 2, gc = lane & 3;
    int am = t >> 1, ah8 = (t & 1) << 3;
    int jr = t >> 2, bq = (t & 3) << 2;
    const float* Bp = g_P + (size_t)(z*LP)*Dm;
    for (int p = 0; p < npass; p++) {
        int g = (mode == 2) ? p : mode;
        const float* Au = g_U + (size_t)(z*2+g)*(LP*NH*Dm);
        float acc[2][4][4] = {};
        for (int s = 0; s < 8; s++) {
            int k0 = s << 4;
            float4 a0 = *(const float4*)&Au[(size_t)(m0+am)*Dm + k0 + ah8];
            float4 a1 = *(const float4*)&Au[(size_t)(m0+am)*Dm + k0 + ah8 + 4];
            float4 b0 = *(const float4*)&Bp[(size_t)(j0+jr)*Dm + k0 + bq];
            float av[8] = {a0.x,a0.y,a0.z,a0.w,a1.x,a1.y,a1.z,a1.w};
#pragma unroll
            for (int q = 0; q < 4; q++) {
                __half h0,l0,h1,l1;
                split2h(av[2*q],   h0, l0);
                split2h(av[2*q+1], h1, l1);
                Ah2[((ah8>>1)+q)*136 + am] = mkh2(h0, h1);
                Al2[((ah8>>1)+q)*136 + am] = mkh2(l0, l1);
            }
            float bv[4] = {b0.x,b0.y,b0.z,b0.w};
#pragma unroll
            for (int q = 0; q < 2; q++) {
                __half h0,l0,h1,l1;
                split2h(bv[2*q],   h0, l0);
                split2h(bv[2*q+1], h1, l1);
                Bh2[((bq>>1)+q)*72 + jr] = mkh2(h0, h1);
                Bl2[((bq>>1)+q)*72 + jr] = mkh2(l0, l1);
            }
            __syncthreads();
            unsigned ah[2][4], al_[2][4], bh[4][2], bl_[4][2];
#pragma unroll
            for (int tm = 0; tm < 2; tm++) {
                int r = wm + tm*16 + gr;
                ah[tm][0] = LDU2(&Ah2[gc*136 + r]);
                ah[tm][1] = LDU2(&Ah2[gc*136 + r + 8]);
                ah[tm][2] = LDU2(&Ah2[(gc+4)*136 + r]);
                ah[tm][3] = LDU2(&Ah2[(gc+4)*136 + r + 8]);
                al_[tm][0] = LDU2(&Al2[gc*136 + r]);
                al_[tm][1] = LDU2(&Al2[gc*136 + r + 8]);
                al_[tm][2] = LDU2(&Al2[(gc+4)*136 + r]);
                al_[tm][3] = LDU2(&Al2[(gc+4)*136 + r + 8]);
            }
#pragma unroll
            for (int tn = 0; tn < 4; tn++) {
                int cn = wn + tn*8 + gr;
                bh[tn][0] = LDU2(&Bh2[gc*72 + cn]);
                bh[tn][1] = LDU2(&Bh2[(gc+4)*72 + cn]);
                bl_[tn][0] = LDU2(&Bl2[gc*72 + cn]);
                bl_[tn][1] = LDU2(&Bl2[(gc+4)*72 + cn]);
            }
#pragma unroll
            for (int tm = 0; tm < 2; tm++)
#pragma unroll
                for (int tn = 0; tn < 4; tn++) {
                    mmah(acc[tm][tn], al_[tm], bh[tn]);
                    mmah(acc[tm][tn], ah[tm], bl_[tn]);
                    mmah(acc[tm][tn], ah[tm], bh[tn]);
                }
            __syncthreads();
        }
#pragma unroll
        for (int tm = 0; tm < 2; tm++)
#pragma unroll
            for (int tn = 0; tn < 4; tn++) {
                int jc = j0 + wn + tn*8 + 2*gc;
#pragma unroll
                for (int half = 0; half < 2; half++) {
                    int m = m0 + wm + tm*16 + gr + half*8;
                    int i = m >> 3, cc = m & 7;
                    size_t off = ((size_t)(z*NH + cc)*LP + i)*LP + jc;
                    float v0 = acc[tm][tn][half*2], v1 = acc[tm][tn][half*2 + 1];
                    if (mode != 2) {
                        float2 w; w.x = v0; w.y = v1;
                        *(float2*)&g_Hmat[off] = w;
                    } else if (p == 0) {
                        float2 w;
                        w.x = (jc     > i) ? v0 : 0.f;
                        w.y = (jc + 1 > i) ? v1 : 0.f;
                        *(float2*)&g_Hmat[off] = w;
                    } else {
                        if (jc     < i) g_Hmat[off]     = v0;
                        if (jc + 1 < i) g_Hmat[off + 1] = v1;
                    }
                }
            }
    }
}

// ---------------- H softmax over j ----------------
__global__ void hsoftmax_kernel() {
    int bid = blockIdx.x;
    int i = bid % Lr;
    int zc = bid / Lr;
    int z = zc >> 3;
    float* row = g_Hmat + (size_t)zc * (LP*LP) + (size_t)i * LP;
    int t = threadIdx.x;
    if (i == 0) {
        for (int j = t; j < Lr; j += 128) row[j] = 0.f;
        return;
    }
    float mi = g_m1[z*LP + i];
    float lv[4];
    float mx = -3.4e38f;
#pragma unroll
    for (int r = 0; r < 4; r++) {
        int j = t + r*128;
        float l = -3.4e38f;
        if (j < Lr) {
            bool ok = (mi != 0.f) && (g_m1[z*LP + j] != 0.f) && (j != i);
            l = ok ? row[j] * 128.f : -1e9f;
        }
        lv[r] = l;
        mx = fmaxf(mx, l);
    }
    __shared__ float shm[4], shs[4];
#pragma unroll
    for (int o = 16; o; o >>= 1) mx = fmaxf(mx, __shfl_xor_sync(0xffffffffu, mx, o));
    if ((t & 31) == 0) shm[t >> 5] = mx;
    __syncthreads();
    mx = fmaxf(fmaxf(shm[0], shm[1]), fmaxf(shm[2], shm[3]));
    float ev[4];
    float s = 0.f;
#pragma unroll
    for (int r = 0; r < 4; r++) {
        int j = t + r*128;
        ev[r] = 0.f;
        if (j < Lr) { ev[r] = __expf(lv[r] - mx); s += ev[r]; }
    }
#pragma unroll
    for (int o = 16; o; o >>= 1) s += __shfl_xor_sync(0xffffffffu, s, o);
    if ((t & 31) == 0) shs[t >> 5] = s;
    __syncthreads();
    s = (shs[0] + shs[1]) + (shs[2] + shs[3]);
    float inv = 1.f / s;
#pragma unroll
    for (int r = 0; r < 4; r++) {
        int j = t + r*128;
        if (j < Lr) row[j] = ev[r] * inv;
    }
}

// =============== G (fp16 3-term): C[i 64 x a 128] = Hsel @ V, warps 2x4, 28 k16-stages ===============
__global__ __launch_bounds__(256) void gemm_g_kernel() {
    __shared__ __half2 Ah2[8*72],  Al2[8*72];    // [kpair(j)][i]
    __shared__ __half2 Bh2[8*136], Bl2[8*136];   // [kpair(j)][a]
    int c = blockIdx.x, i0 = blockIdx.y*64, z = blockIdx.z;
    const float* Hmp = g_Hmat + (size_t)(z*NH + c)*(LP*LP);
    int t = threadIdx.x, lane = t & 31, warp = t >> 5;
    int wm = (warp >> 2)*32, wn = (warp & 3)*32;
    int gr = lane >> 2, gc = lane & 3;
    int ir = t >> 2, jq = (t & 3) << 2;
    int jp = t >> 5, bn = lane << 2;
    float acc[2][4][4] = {};
    for (int ss = 0; ss < 28; ss++) {
        int j0s = ss << 4;
        int mode = (j0s >= i0 + 64) ? 0 : ((j0s + 16 <= i0) ? 1 : 2);
        int npass = (mode == 2) ? 2 : 1;
        float4 hv = *(const float4*)&Hmp[(size_t)(i0 + ir)*LP + j0s + jq];
        float h4[4] = {hv.x, hv.y, hv.z, hv.w};
        for (int p = 0; p < npass; p++) {
            int g = (mode == 2) ? p : mode;
            // A: masked H split -> [kpair][i]
            {
                int ig = i0 + ir;
                float mv[4];
#pragma unroll
                for (int q = 0; q < 4; q++) {
                    float val = h4[q];
                    if (mode == 2) {
                        int jg = j0s + jq + q;
                        bool keep = (g == 0) ? (jg > ig) : (jg < ig);
                        if (!keep) val = 0.f;
                    }
                    mv[q] = val;
                }
#pragma unroll
                for (int q = 0; q < 2; q++) {
                    __half h0,l0,h1,l1;
                    split2h(mv[2*q],   h0, l0);
                    split2h(mv[2*q+1], h1, l1);
                    Ah2[((jq>>1)+q)*72 + ir] = mkh2(h0, h1);
                    Al2[((jq>>1)+q)*72 + ir] = mkh2(l0, l1);
                }
            }
            // B: V rows (j pairs) -> [kpair][a]
            {
                const float* Vp = g_V + (size_t)(z*2+g)*(LP*NH*Dm) + (size_t)c*Dm;
                float4 v0 = *(const float4*)&Vp[(size_t)(j0s + 2*jp)*1024 + bn];
                float4 v1 = *(const float4*)&Vp[(size_t)(j0s + 2*jp + 1)*1024 + bn];
                float r0[4] = {v0.x,v0.y,v0.z,v0.w};
                float r1[4] = {v1.x,v1.y,v1.z,v1.w};
#pragma unroll
                for (int q = 0; q < 4; q++) {
                    __half h0,l0,h1,l1;
                    split2h(r0[q], h0, l0);
                    split2h(r1[q], h1, l1);
                    Bh2[jp*136 + bn + q] = mkh2(h0, h1);
                    Bl2[jp*136 + bn + q] = mkh2(l0, l1);
                }
            }
            __syncthreads();
            unsigned ah[2][4], al_[2][4], bh[4][2], bl_[4][2];
#pragma unroll
            for (int tm = 0; tm < 2; tm++) {
                int r = wm + tm*16 + gr;
                ah[tm][0] = LDU2(&Ah2[gc*72 + r]);
                ah[tm][1] = LDU2(&Ah2[gc*72 + r + 8]);
                ah[tm][2] = LDU2(&Ah2[(gc+4)*72 + r]);
                ah[tm][3] = LDU2(&Ah2[(gc+4)*72 + r + 8]);
                al_[tm][0] = LDU2(&Al2[gc*72 + r]);
                al_[tm][1] = LDU2(&Al2[gc*72 + r + 8]);
                al_[tm][2] = LDU2(&Al2[(gc+4)*72 + r]);
                al_[tm][3] = LDU2(&Al2[(gc+4)*72 + r + 8]);
            }
#pragma unroll
            for (int tn = 0; tn < 4; tn++) {
                int cn = wn + tn*8 + gr;
                bh[tn][0] = LDU2(&Bh2[gc*136 + cn]);
                bh[tn][1] = LDU2(&Bh2[(gc+4)*136 + cn]);
                bl_[tn][0] = LDU2(&Bl2[gc*136 + cn]);
                bl_[tn][1] = LDU2(&Bl2[(gc+4)*136 + cn]);
            }
#pragma unroll
            for (int tm = 0; tm < 2; tm++)
#pragma unroll
                for (int tn = 0; tn < 4; tn++) {
                    mmah(acc[tm][tn], al_[tm], bh[tn]);
                    mmah(acc[tm][tn], ah[tm], bl_[tn]);
                    mmah(acc[tm][tn], ah[tm], bh[tn]);
                }
            __syncthreads();
        }
    }
    float* out = &g_Gp[((size_t)(z*NH + c)*LP + i0)*Dm];
#pragma unroll
    for (int tm = 0; tm < 2; tm++)
#pragma unroll
        for (int tn = 0; tn < 4; tn++) {
            int r  = wm + tm*16 + gr;
            int cn = wn + tn*8 + 2*gc;
            float2 w0; w0.x = acc[tm][tn][0]; w0.y = acc[tm][tn][1];
            float2 w1; w1.x = acc[tm][tn][2]; w1.y = acc[tm][tn][3];
            *(float2*)&out[(size_t)r*Dm + cn]     = w0;
            *(float2*)&out[(size_t)(r+8)*Dm + cn] = w1;
        }
}

// =============== Hm (fp16 3-term): C[j 64 x b 128] = Hsel^T @ U, warps 2x4, 28 k16-stages ===============
__global__ __launch_bounds__(256) void gemm_hm_kernel() {
    __shared__ __half2 Ah2[8*72],  Al2[8*72];    // [kpair(i)][j]
    __shared__ __half2 Bh2[8*136], Bl2[8*136];   // [kpair(i)][b]
    int c = blockIdx.x, j0 = blockIdx.y*64, z = blockIdx.z;
    const float* Hmp = g_Hmat + (size_t)(z*NH + c)*(LP*LP);
    int t = threadIdx.x, lane = t & 31, warp = t >> 5;
    int wm = (warp >> 2)*32, wn = (warp & 3)*32;
    int gr = lane >> 2, gc = lane & 3;
    int ip = t >> 5, jc2 = lane << 1;
    int bn = lane << 2;
    float acc[2][4][4] = {};
    for (int ss = 0; ss < 28; ss++) {
        int i0s = ss << 4;
        int mode = (i0s + 16 <= j0) ? 0 : ((i0s >= j0 + 64) ? 1 : 2);
        int npass = (mode == 2) ? 2 : 1;
        int ig0 = i0s + 2*ip, ig1 = ig0 + 1;
        float2 hr0 = *(const float2*)&Hmp[(size_t)ig0*LP + j0 + jc2];
        float2 hr1 = *(const float2*)&Hmp[(size_t)ig1*LP + j0 + jc2];
        for (int p = 0; p < npass; p++) {
            int g = (mode == 2) ? p : mode;
            // A: masked H^T split -> [kpair(i)][j]
            {
                float a00 = hr0.x, a01 = hr0.y, a10 = hr1.x, a11 = hr1.y;
                if (mode == 2) {
                    int jg0 = j0 + jc2, jg1 = jg0 + 1;
                    if (!((g == 0) ? (ig0 < jg0) : (ig0 > jg0))) a00 = 0.f;
                    if (!((g == 0) ? (ig0 < jg1) : (ig0 > jg1))) a01 = 0.f;
                    if (!((g == 0) ? (ig1 < jg0) : (ig1 > jg0))) a10 = 0.f;
                    if (!((g == 0) ? (ig1 < jg1) : (ig1 > jg1))) a11 = 0.f;
                }
                __half h00,l00,h01,l01,h10,l10,h11,l11;
                split2h(a00, h00, l00); split2h(a01, h01, l01);
                split2h(a10, h10, l10); split2h(a11, h11, l11);
                Ah2[ip*72 + jc2]     = mkh2(h00, h10);
                Ah2[ip*72 + jc2 + 1] = mkh2(h01, h11);
                Al2[ip*72 + jc2]     = mkh2(l00, l10);
                Al2[ip*72 + jc2 + 1] = mkh2(l01, l11);
            }
            // B: U rows (i pairs) -> [kpair(i)][b]
            {
                const float* Up = g_U + (size_t)(z*2+g)*(LP*NH*Dm) + (size_t)c*Dm;
                float4 u0 = *(const float4*)&Up[(size_t)(i0s + 2*ip)*1024 + bn];
                float4 u1 = *(const float4*)&Up[(size_t)(i0s + 2*ip + 1)*1024 + bn];
                float r0[4] = {u0.x,u0.y,u0.z,u0.w};
                float r1[4] = {u1.x,u1.y,u1.z,u1.w};
#pragma unroll
                for (int q = 0; q < 4; q++) {
                    __half h0,l0,h1,l1;
                    split2h(r0[q], h0, l0);
                    split2h(r1[q], h1, l1);
                    Bh2[ip*136 + bn + q] = mkh2(h0, h1);
                    Bl2[ip*136 + bn + q] = mkh2(l0, l1);
                }
            }
            __syncthreads();
            unsigned ah[2][4], al_[2][4], bh[4][2], bl_[4][2];
#pragma unroll
            for (int tm = 0; tm < 2; tm++) {
                int r = wm + tm*16 + gr;   // j index
                ah[tm][0] = LDU2(&Ah2[gc*72 + r]);
                ah[tm][1] = LDU2(&Ah2[gc*72 + r + 8]);
                ah[tm][2] = LDU2(&Ah2[(gc+4)*72 + r]);
                ah[tm][3] = LDU2(&Ah2[(gc+4)*72 + r + 8]);
                al_[tm][0] = LDU2(&Al2[gc*72 + r]);
                al_[tm][1] = LDU2(&Al2[gc*72 + r + 8]);
                al_[tm][2] = LDU2(&Al2[(gc+4)*72 + r]);
                al_[tm][3] = LDU2(&Al2[(gc+4)*72 + r + 8]);
            }
#pragma unroll
            for (int tn = 0; tn < 4; tn++) {
                int cn = wn + tn*8 + gr;
                bh[tn][0] = LDU2(&Bh2[gc*136 + cn]);
                bh[tn][1] = LDU2(&Bh2[(gc+4)*136 + cn]);
                bl_[tn][0] = LDU2(&Bl2[gc*136 + cn]);
                bl_[tn][1] = LDU2(&Bl2[(gc+4)*136 + cn]);
            }
#pragma unroll
            for (int tm = 0; tm < 2; tm++)
#pragma unroll
                for (int tn = 0; tn < 4; tn++) {
                    mmah(acc[tm][tn], al_[tm], bh[tn]);
                    mmah(acc[tm][tn], ah[tm], bl_[tn]);
                    mmah(acc[tm][tn], ah[tm], bh[tn]);
                }
            __syncthreads();
        }
    }
    float* out = &g_Hp[((size_t)(z*NH + c)*LP + j0)*Dm];
#pragma unroll
    for (int tm = 0; tm < 2; tm++)
#pragma unroll
        for (int tn = 0; tn < 4; tn++) {
            int r  = wm + tm*16 + gr;
            int cn = wn + tn*8 + 2*gc;
            float2 w0; w0.x = acc[tm][tn][0]; w0.y = acc[tm][tn][1];
            float2 w1; w1.x = acc[tm][tn][2]; w1.y = acc[tm][tn][3];
            *(float2*)&out[(size_t)r*Dm + cn]     = w0;
            *(float2*)&out[(size_t)(r+8)*Dm + cn] = w1;
        }
}

// ---------------- q_z = (unary + sum_c Gp + sum_c Hp) * m1 ----------------
__global__ void reduce_qz_kernel() {
    int idx = blockIdx.x * blockDim.x + threadIdx.x;
    if (idx >= Bz*LP*Dm) return;
    int d = idx & 127;
    int zi = idx >> 7;
    int i = zi % LP, z = zi / LP;
    float s = g_unary[idx];
#pragma unroll
    for (int c = 0; c < NH; c++) {
        size_t o = ((size_t)(z*NH + c)*LP + i)*Dm + d;
        s += g_Gp[o] + g_Hp[o];
    }
    g_qz[idx] = s * g_m1[zi];
}

__global__ void out_kernel(float* __restrict__ out) {
    int idx = blockIdx.x * blockDim.x + threadIdx.x;
    if (idx >= Bz*L0c*Dm) return;
    int d = idx & 127;
    int zt = idx >> 7;
    int tt = zt % L0c, z = zt / L0c;
    out[idx] = g_qz[(z*LP + 1 + tt)*Dm + d];
}

extern "C" void kernel_launch(void* const* d_in, const int* in_sizes, int n_in,
                              void* d_out, int out_size) {
    const float* x = nullptr;
    const float* mask = nullptr;
    const float* tern = nullptr;
    for (int i = 0; i < n_in; i++) {
        if (in_sizes[i] == Bz*L0c*Dm)       x    = (const float*)d_in[i];
        else if (in_sizes[i] == Bz*L0c)     mask = (const float*)d_in[i];
        else if (in_sizes[i] == 2*Dm*Dm*NH) tern = (const float*)d_in[i];
    }
    if (!x || !mask || !tern) return;

    prep_unary_kernel<<<(Bz*LP*Dm + 255)/256, 256>>>(x, mask);
    zero_ppad_kernel<<<(128*Dm + 255)/256, 256>>>();
    prep_T_kernel<<<(2*Dm*Dm*NH + 255)/256, 256>>>(tern);

    for (int it = 0; it < NIT; it++) {
        softmax_p_kernel<<<Bz*Lr, 128>>>();
        gemm_uv_kernel<<<dim3(8, 7, 32), 256>>>();
        gemm_f_kernel<<<dim3(7, 28, Bz), 256>>>();
        hsoftmax_kernel<<<Bz*NH*Lr, 128>>>();
        gemm_g_kernel<<<dim3(NH, 7, Bz), 256>>>();
        gemm_hm_kernel<<<dim3(NH, 7, Bz), 256>>>();
        reduce_qz_kernel<<<(Bz*LP*Dm + 255)/256, 256>>>();
    }
    out_kernel<<<(Bz*L0c*Dm + 255)/256, 256>>>((float*)d_out);
}

// round 13
// speedup vs baseline: 1.9071x; 1.1332x over previous
#include <cuda_runtime.h>
#include <cuda_fp16.h>
#include <cstdint>

#define Bz 8
#define L0c 384
#define Lr 385
#define LP 448
#define Dm 128
#define NH 8
#define NIT 4

// ---------------- scratch (all fp32, R2 layouts) ----------------
__device__ float g_unary[Bz*LP*Dm];
__device__ float g_qz[Bz*LP*Dm];
__device__ float g_P[(Bz*LP + 128)*Dm];
__device__ float g_m1[Bz*LP];
__device__ float g_Tu[2*Dm*NH*Dm];        // [k][a][c][b]
__device__ float g_Tv[2*Dm*NH*Dm];        // [k][b][c][a]
__device__ float g_U[Bz*2*LP*NH*Dm];      // [z][g][i][(c,b)] == stacked m=(i*8+c)
__device__ float g_V[Bz*2*LP*NH*Dm];      // [z][g][j][(c,a)]
__device__ float g_Hmat[(size_t)Bz*NH*LP*LP];
__device__ float g_Gp[Bz*NH*LP*Dm];
__device__ float g_Hp[Bz*NH*LP*Dm];

// ---------------- fp16 split helpers ----------------
__device__ __forceinline__ void split2h(float x, __half& h, __half& l) {
    h = __float2half_rn(x);
    l = __float2half_rn(x - __half2float(h));
}
__device__ __forceinline__ void mmah(float* c, const unsigned* a, const unsigned* b) {
    asm volatile(
        "mma.sync.aligned.m16n8k16.row.col.f32.f16.f16.f32 "
        "{%0,%1,%2,%3}, {%4,%5,%6,%7}, {%8,%9}, {%0,%1,%2,%3};"
        : "+f"(c[0]), "+f"(c[1]), "+f"(c[2]), "+f"(c[3])
        : "r"(a[0]), "r"(a[1]), "r"(a[2]), "r"(a[3]), "r"(b[0]), "r"(b[1]));
}
__device__ __forceinline__ __half2 mkh2(__half a, __half b) { __half2 r; r.x = a; r.y = b; return r; }
#define LDU2(p) (*(const unsigned*)(p))

// ---------------- prep ----------------
__global__ void prep_unary_kernel(const float* __restrict__ x,
                                  const float* __restrict__ mask) {
    int idx = blockIdx.x * blockDim.x + threadIdx.x;
    if (idx >= Bz*LP*Dm) return;
    int d = idx & 127;
    int zi = idx >> 7;
    int i = zi % LP, z = zi / LP;
    float v = 0.f;
    if (i >= 1 && i < Lr) v = x[(z*L0c + (i-1))*Dm + d];
    float m = (i == 0) ? 1.f : ((i < Lr) ? mask[z*L0c + (i-1)] : 0.f);
    g_unary[idx] = v;
    g_qz[idx]    = v * m;
    g_P[idx]     = 0.f;
    if (d == 0) g_m1[zi] = m;
}

__global__ void zero_ppad_kernel() {
    int idx = blockIdx.x * blockDim.x + threadIdx.x;
    if (idx < 128*Dm) g_P[Bz*LP*Dm + idx] = 0.f;
}

__global__ void prep_T_kernel(const float* __restrict__ tern) {
    int idx = blockIdx.x * blockDim.x + threadIdx.x;
    if (idx >= 2*Dm*Dm*NH) return;
    int c = idx & 7;
    int r = idx >> 3;
    int b = r & 127; r >>= 7;
    int a = r & 127;
    int k = r >> 7;
    float v = tern[idx];
    g_Tu[((k*Dm + a)*NH + c)*Dm + b] = v;
    g_Tv[((k*Dm + b)*NH + c)*Dm + a] = v;
}

// ---------------- softmax over d ----------------
__global__ void softmax_p_kernel() {
    int row = blockIdx.x;
    int z = row / Lr, i = row - z*Lr;
    const float* src = g_qz + (z*LP + i)*Dm;
    int t = threadIdx.x;
    float v = src[t];
    __shared__ float shm[4], shs[4];
    float m = v;
#pragma unroll
    for (int o = 16; o; o >>= 1) m = fmaxf(m, __shfl_xor_sync(0xffffffffu, m, o));
    if ((t & 31) == 0) shm[t >> 5] = m;
    __syncthreads();
    m = fmaxf(fmaxf(shm[0], shm[1]), fmaxf(shm[2], shm[3]));
    float e = __expf(v - m);
    float s = e;
#pragma unroll
    for (int o = 16; o; o >>= 1) s += __shfl_xor_sync(0xffffffffu, s, o);
    if ((t & 31) == 0) shs[t >> 5] = s;
    __syncthreads();
    s = (shs[0] + shs[1]) + (shs[2] + shs[3]);
    g_P[(z*LP + i)*Dm + t] = e / s * g_m1[z*LP + i];
}

// =============== UV (fp16 3-term): C[448x1024] = P @ T, tile 64x128, warps 2x4 ===============
__global__ __launch_bounds__(256) void gemm_uv_kernel() {
    __shared__ __half2 Ah2[8*72],  Al2[8*72];    // [kpair][m 64]
    __shared__ __half2 Bh2[8*136], Bl2[8*136];   // [kpair][n 128]
    int inst = blockIdx.z;
    int uv = inst & 1, kg = (inst >> 1) & 1, z = inst >> 2;
    const float* A  = g_P + (size_t)(z*LP)*Dm;
    const float* Bm = (uv ? g_Tv : g_Tu) + kg * (Dm*NH*Dm);
    float*       C  = (uv ? g_V : g_U) + (size_t)(z*2 + kg) * (LP*NH*Dm);
    int m0 = blockIdx.y * 64, n0 = blockIdx.x * 128;
    int t = threadIdx.x, lane = t & 31, warp = t >> 5;
    int wm = (warp >> 2)*32, wn = (warp & 3)*32;
    int gr = lane >> 2, gc = lane & 3;
    int ar = t >> 2, aq = (t & 3) << 2;
    int kp = t >> 5, bn = lane << 2;
    float acc[2][4][4] = {};
    for (int s = 0; s < 8; s++) {
        int k0 = s << 4;
        // A: P rows [m][k16] -> [kpair][m]
        {
            float4 av = *(const float4*)&A[(size_t)(m0 + ar)*Dm + k0 + aq];
            float pv[4] = {av.x, av.y, av.z, av.w};
#pragma unroll
            for (int q = 0; q < 2; q++) {
                __half h0,l0,h1,l1;
                split2h(pv[2*q],   h0, l0);
                split2h(pv[2*q+1], h1, l1);
                Ah2[((aq>>1)+q)*72 + ar] = mkh2(h0, h1);
                Al2[((aq>>1)+q)*72 + ar] = mkh2(l0, l1);
            }
        }
        // B: T row pairs (k0+2kp, k0+2kp+1) -> [kpair][n]
        {
            float4 r0 = *(const float4*)&Bm[(size_t)(k0 + 2*kp)*1024 + n0 + bn];
            float4 r1 = *(const float4*)&Bm[(size_t)(k0 + 2*kp + 1)*1024 + n0 + bn];
            float v0[4] = {r0.x,r0.y,r0.z,r0.w};
            float v1[4] = {r1.x,r1.y,r1.z,r1.w};
#pragma unroll
            for (int q = 0; q < 4; q++) {
                __half h0,l0,h1,l1;
                split2h(v0[q], h0, l0);
                split2h(v1[q], h1, l1);
                Bh2[kp*136 + bn + q] = mkh2(h0, h1);
                Bl2[kp*136 + bn + q] = mkh2(l0, l1);
            }
        }
        __syncthreads();
        unsigned ah[2][4], al_[2][4], bh[4][2], bl_[4][2];
#pragma unroll
        for (int tm = 0; tm < 2; tm++) {
            int r = wm + tm*16 + gr;
            ah[tm][0] = LDU2(&Ah2[gc*72 + r]);
            ah[tm][1] = LDU2(&Ah2[gc*72 + r + 8]);
            ah[tm][2] = LDU2(&Ah2[(gc+4)*72 + r]);
            ah[tm][3] = LDU2(&Ah2[(gc+4)*72 + r + 8]);
            al_[tm][0] = LDU2(&Al2[gc*72 + r]);
            al_[tm][1] = LDU2(&Al2[gc*72 + r + 8]);
            al_[tm][2] = LDU2(&Al2[(gc+4)*72 + r]);
            al_[tm][3] = LDU2(&Al2[(gc+4)*72 + r + 8]);
        }
#pragma unroll
        for (int tn = 0; tn < 4; tn++) {
            int cn = wn + tn*8 + gr;
            bh[tn][0] = LDU2(&Bh2[gc*136 + cn]);
            bh[tn][1] = LDU2(&Bh2[(gc+4)*136 + cn]);
            bl_[tn][0] = LDU2(&Bl2[gc*136 + cn]);
            bl_[tn][1] = LDU2(&Bl2[(gc+4)*136 + cn]);
        }
#pragma unroll
        for (int tm = 0; tm < 2; tm++)
#pragma unroll
            for (int tn = 0; tn < 4; tn++) {
                mmah(acc[tm][tn], al_[tm], bh[tn]);
                mmah(acc[tm][tn], ah[tm], bl_[tn]);
                mmah(acc[tm][tn], ah[tm], bh[tn]);
            }
        __syncthreads();
    }
#pragma unroll
    for (int tm = 0; tm < 2; tm++)
#pragma unroll
        for (int tn = 0; tn < 4; tn++) {
            int r  = m0 + wm + tm*16 + gr;
            int cn = n0 + wn + tn*8 + 2*gc;
            float2 w0; w0.x = acc[tm][tn][0]; w0.y = acc[tm][tn][1];
            float2 w1; w1.x = acc[tm][tn][2]; w1.y = acc[tm][tn][3];
            *(float2*)&C[(size_t)r*1024 + cn]     = w0;
            *(float2*)&C[(size_t)(r+8)*1024 + cn] = w1;
        }
}

// =============== F (fp16 3-term): C[m=3584 x j] = U[m][b].P[j][b] NT, tile 128x64, warps 4x2 ===============
__global__ __launch_bounds__(256) void gemm_f_kernel() {
    __shared__ __half2 Ah2[8*136], Al2[8*136];   // [kpair][m]
    __shared__ __half2 Bh2[8*72],  Bl2[8*72];    // [kpair][j]
    int z = blockIdx.z;
    int m0 = blockIdx.y*128, j0 = blockIdx.x*64;
    int ilo = m0 >> 3;
    int mode = (j0 >= ilo + 16) ? 0 : ((j0 + 64 <= ilo) ? 1 : 2);
    int npass = (mode == 2) ? 2 : 1;
    int t = threadIdx.x, lane = t & 31, warp = t >> 5;
    int wm = (warp >> 1)*32, wn = (warp & 1)*32;
    int gr = lane >> 2, gc = lane & 3;
    int am = t >> 1, ah8 = (t & 1) << 3;
    int jr = t >> 2, bq = (t & 3) << 2;
    const float* Bp = g_P + (size_t)(z*LP)*Dm;
    for (int p = 0; p < npass; p++) {
        int g = (mode == 2) ? p : mode;
        const float* Au = g_U + (size_t)(z*2+g)*(LP*NH*Dm);
        float acc[2][4][4] = {};
        for (int s = 0; s < 8; s++) {
            int k0 = s << 4;
            float4 a0 = *(const float4*)&Au[(size_t)(m0+am)*Dm + k0 + ah8];
            float4 a1 = *(const float4*)&Au[(size_t)(m0+am)*Dm + k0 + ah8 + 4];
            float4 b0 = *(const float4*)&Bp[(size_t)(j0+jr)*Dm + k0 + bq];
            float av[8] = {a0.x,a0.y,a0.z,a0.w,a1.x,a1.y,a1.z,a1.w};
#pragma unroll
            for (int q = 0; q < 4; q++) {
                __half h0,l0,h1,l1;
                split2h(av[2*q],   h0, l0);
                split2h(av[2*q+1], h1, l1);
                Ah2[((ah8>>1)+q)*136 + am] = mkh2(h0, h1);
                Al2[((ah8>>1)+q)*136 + am] = mkh2(l0, l1);
            }
            float bv[4] = {b0.x,b0.y,b0.z,b0.w};
#pragma unroll
            for (int q = 0; q < 2; q++) {
                __half h0,l0,h1,l1;
                split2h(bv[2*q],   h0, l0);
                split2h(bv[2*q+1], h1, l1);
                Bh2[((bq>>1)+q)*72 + jr] = mkh2(h0, h1);
                Bl2[((bq>>1)+q)*72 + jr] = mkh2(l0, l1);
            }
            __syncthreads();
            unsigned ah[2][4], al_[2][4], bh[4][2], bl_[4][2];
#pragma unroll
            for (int tm = 0; tm < 2; tm++) {
                int r = wm + tm*16 + gr;
                ah[tm][0] = LDU2(&Ah2[gc*136 + r]);
                ah[tm][1] = LDU2(&Ah2[gc*136 + r + 8]);
                ah[tm][2] = LDU2(&Ah2[(gc+4)*136 + r]);
                ah[tm][3] = LDU2(&Ah2[(gc+4)*136 + r + 8]);
                al_[tm][0] = LDU2(&Al2[gc*136 + r]);
                al_[tm][1] = LDU2(&Al2[gc*136 + r + 8]);
                al_[tm][2] = LDU2(&Al2[(gc+4)*136 + r]);
                al_[tm][3] = LDU2(&Al2[(gc+4)*136 + r + 8]);
            }
#pragma unroll
            for (int tn = 0; tn < 4; tn++) {
                int cn = wn + tn*8 + gr;
                bh[tn][0] = LDU2(&Bh2[gc*72 + cn]);
                bh[tn][1] = LDU2(&Bh2[(gc+4)*72 + cn]);
                bl_[tn][0] = LDU2(&Bl2[gc*72 + cn]);
                bl_[tn][1] = LDU2(&Bl2[(gc+4)*72 + cn]);
            }
#pragma unroll
            for (int tm = 0; tm < 2; tm++)
#pragma unroll
                for (int tn = 0; tn < 4; tn++) {
                    mmah(acc[tm][tn], al_[tm], bh[tn]);
                    mmah(acc[tm][tn], ah[tm], bl_[tn]);
                    mmah(acc[tm][tn], ah[tm], bh[tn]);
                }
            __syncthreads();
        }
#pragma unroll
        for (int tm = 0; tm < 2; tm++)
#pragma unroll
            for (int tn = 0; tn < 4; tn++) {
                int jc = j0 + wn + tn*8 + 2*gc;
#pragma unroll
                for (int half = 0; half < 2; half++) {
                    int m = m0 + wm + tm*16 + gr + half*8;
                    int i = m >> 3, cc = m & 7;
                    size_t off = ((size_t)(z*NH + cc)*LP + i)*LP + jc;
                    float v0 = acc[tm][tn][half*2], v1 = acc[tm][tn][half*2 + 1];
                    if (mode != 2) {
                        float2 w; w.x = v0; w.y = v1;
                        *(float2*)&g_Hmat[off] = w;
                    } else if (p == 0) {
                        float2 w;
                        w.x = (jc     > i) ? v0 : 0.f;
                        w.y = (jc + 1 > i) ? v1 : 0.f;
                        *(float2*)&g_Hmat[off] = w;
                    } else {
                        if (jc     < i) g_Hmat[off]     = v0;
                        if (jc + 1 < i) g_Hmat[off + 1] = v1;
                    }
                }
            }
    }
}

// ---------------- H softmax over j ----------------
__global__ void hsoftmax_kernel() {
    int bid = blockIdx.x;
    int i = bid % Lr;
    int zc = bid / Lr;
    int z = zc >> 3;
    float* row = g_Hmat + (size_t)zc * (LP*LP) + (size_t)i * LP;
    int t = threadIdx.x;
    if (i == 0) {
        for (int j = t; j < Lr; j += 128) row[j] = 0.f;
        return;
    }
    float mi = g_m1[z*LP + i];
    float lv[4];
    float mx = -3.4e38f;
#pragma unroll
    for (int r = 0; r < 4; r++) {
        int j = t + r*128;
        float l = -3.4e38f;
        if (j < Lr) {
            bool ok = (mi != 0.f) && (g_m1[z*LP + j] != 0.f) && (j != i);
            l = ok ? row[j] * 128.f : -1e9f;
        }
        lv[r] = l;
        mx = fmaxf(mx, l);
    }
    __shared__ float shm[4], shs[4];
#pragma unroll
    for (int o = 16; o; o >>= 1) mx = fmaxf(mx, __shfl_xor_sync(0xffffffffu, mx, o));
    if ((t & 31) == 0) shm[t >> 5] = mx;
    __syncthreads();
    mx = fmaxf(fmaxf(shm[0], shm[1]), fmaxf(shm[2], shm[3]));
    float ev[4];
    float s = 0.f;
#pragma unroll
    for (int r = 0; r < 4; r++) {
        int j = t + r*128;
        ev[r] = 0.f;
        if (j < Lr) { ev[r] = __expf(lv[r] - mx); s += ev[r]; }
    }
#pragma unroll
    for (int o = 16; o; o >>= 1) s += __shfl_xor_sync(0xffffffffu, s, o);
    if ((t & 31) == 0) shs[t >> 5] = s;
    __syncthreads();
    s = (shs[0] + shs[1]) + (shs[2] + shs[3]);
    float inv = 1.f / s;
#pragma unroll
    for (int r = 0; r < 4; r++) {
        int j = t + r*128;
        if (j < Lr) row[j] = ev[r] * inv;
    }
}

// =============== G (fp16 3-term): C[i 64 x a 128] = Hsel @ V, warps 2x4, 28 k16-stages ===============
__global__ __launch_bounds__(256) void gemm_g_kernel() {
    __shared__ __half2 Ah2[8*72],  Al2[8*72];    // [kpair(j)][i]
    __shared__ __half2 Bh2[8*136], Bl2[8*136];   // [kpair(j)][a]
    int c = blockIdx.x, i0 = blockIdx.y*64, z = blockIdx.z;
    const float* Hmp = g_Hmat + (size_t)(z*NH + c)*(LP*LP);
    int t = threadIdx.x, lane = t & 31, warp = t >> 5;
    int wm = (warp >> 2)*32, wn = (warp & 3)*32;
    int gr = lane >> 2, gc = lane & 3;
    int ir = t >> 2, jq = (t & 3) << 2;
    int jp = t >> 5, bn = lane << 2;
    float acc[2][4][4] = {};
    for (int ss = 0; ss < 28; ss++) {
        int j0s = ss << 4;
        int mode = (j0s >= i0 + 64) ? 0 : ((j0s + 16 <= i0) ? 1 : 2);
        int npass = (mode == 2) ? 2 : 1;
        float4 hv = *(const float4*)&Hmp[(size_t)(i0 + ir)*LP + j0s + jq];
        float h4[4] = {hv.x, hv.y, hv.z, hv.w};
        for (int p = 0; p < npass; p++) {
            int g = (mode == 2) ? p : mode;
            {
                int ig = i0 + ir;
                float mv[4];
#pragma unroll
                for (int q = 0; q < 4; q++) {
                    float val = h4[q];
                    if (mode == 2) {
                        int jg = j0s + jq + q;
                        bool keep = (g == 0) ? (jg > ig) : (jg < ig);
                        if (!keep) val = 0.f;
                    }
                    mv[q] = val;
                }
#pragma unroll
                for (int q = 0; q < 2; q++) {
                    __half h0,l0,h1,l1;
                    split2h(mv[2*q],   h0, l0);
                    split2h(mv[2*q+1], h1, l1);
                    Ah2[((jq>>1)+q)*72 + ir] = mkh2(h0, h1);
                    Al2[((jq>>1)+q)*72 + ir] = mkh2(l0, l1);
                }
            }
            {
                const float* Vp = g_V + (size_t)(z*2+g)*(LP*NH*Dm) + (size_t)c*Dm;
                float4 v0 = *(const float4*)&Vp[(size_t)(j0s + 2*jp)*1024 + bn];
                float4 v1 = *(const float4*)&Vp[(size_t)(j0s + 2*jp + 1)*1024 + bn];
                float r0[4] = {v0.x,v0.y,v0.z,v0.w};
                float r1[4] = {v1.x,v1.y,v1.z,v1.w};
#pragma unroll
                for (int q = 0; q < 4; q++) {
                    __half h0,l0,h1,l1;
                    split2h(r0[q], h0, l0);
                    split2h(r1[q], h1, l1);
                    Bh2[jp*136 + bn + q] = mkh2(h0, h1);
                    Bl2[jp*136 + bn + q] = mkh2(l0, l1);
                }
            }
            __syncthreads();
            unsigned ah[2][4], al_[2][4], bh[4][2], bl_[4][2];
#pragma unroll
            for (int tm = 0; tm < 2; tm++) {
                int r = wm + tm*16 + gr;
                ah[tm][0] = LDU2(&Ah2[gc*72 + r]);
                ah[tm][1] = LDU2(&Ah2[gc*72 + r + 8]);
                ah[tm][2] = LDU2(&Ah2[(gc+4)*72 + r]);
                ah[tm][3] = LDU2(&Ah2[(gc+4)*72 + r + 8]);
                al_[tm][0] = LDU2(&Al2[gc*72 + r]);
                al_[tm][1] = LDU2(&Al2[gc*72 + r + 8]);
                al_[tm][2] = LDU2(&Al2[(gc+4)*72 + r]);
                al_[tm][3] = LDU2(&Al2[(gc+4)*72 + r + 8]);
            }
#pragma unroll
            for (int tn = 0; tn < 4; tn++) {
                int cn = wn + tn*8 + gr;
                bh[tn][0] = LDU2(&Bh2[gc*136 + cn]);
                bh[tn][1] = LDU2(&Bh2[(gc+4)*136 + cn]);
                bl_[tn][0] = LDU2(&Bl2[gc*136 + cn]);
                bl_[tn][1] = LDU2(&Bl2[(gc+4)*136 + cn]);
            }
#pragma unroll
            for (int tm = 0; tm < 2; tm++)
#pragma unroll
                for (int tn = 0; tn < 4; tn++) {
                    mmah(acc[tm][tn], al_[tm], bh[tn]);
                    mmah(acc[tm][tn], ah[tm], bl_[tn]);
                    mmah(acc[tm][tn], ah[tm], bh[tn]);
                }
            __syncthreads();
        }
    }
    float* out = &g_Gp[((size_t)(z*NH + c)*LP + i0)*Dm];
#pragma unroll
    for (int tm = 0; tm < 2; tm++)
#pragma unroll
        for (int tn = 0; tn < 4; tn++) {
            int r  = wm + tm*16 + gr;
            int cn = wn + tn*8 + 2*gc;
            float2 w0; w0.x = acc[tm][tn][0]; w0.y = acc[tm][tn][1];
            float2 w1; w1.x = acc[tm][tn][2]; w1.y = acc[tm][tn][3];
            *(float2*)&out[(size_t)r*Dm + cn]     = w0;
            *(float2*)&out[(size_t)(r+8)*Dm + cn] = w1;
        }
}

// =============== Hm (fp16 3-term): C[j 64 x b 128] = Hsel^T @ U, warps 2x4, 28 k16-stages ===============
__global__ __launch_bounds__(256) void gemm_hm_kernel() {
    __shared__ __half2 Ah2[8*72],  Al2[8*72];    // [kpair(i)][j]
    __shared__ __half2 Bh2[8*136], Bl2[8*136];   // [kpair(i)][b]
    int c = blockIdx.x, j0 = blockIdx.y*64, z = blockIdx.z;
    const float* Hmp = g_Hmat + (size_t)(z*NH + c)*(LP*LP);
    int t = threadIdx.x, lane = t & 31, warp = t >> 5;
    int wm = (warp >> 2)*32, wn = (warp & 3)*32;
    int gr = lane >> 2, gc = lane & 3;
    int ip = t >> 5, jc2 = lane << 1;
    int bn = lane << 2;
    float acc[2][4][4] = {};
    for (int ss = 0; ss < 28; ss++) {
        int i0s = ss << 4;
        int mode = (i0s + 16 <= j0) ? 0 : ((i0s >= j0 + 64) ? 1 : 2);
        int npass = (mode == 2) ? 2 : 1;
        int ig0 = i0s + 2*ip, ig1 = ig0 + 1;
        float2 hr0 = *(const float2*)&Hmp[(size_t)ig0*LP + j0 + jc2];
        float2 hr1 = *(const float2*)&Hmp[(size_t)ig1*LP + j0 + jc2];
        for (int p = 0; p < npass; p++) {
            int g = (mode == 2) ? p : mode;
            {
                float a00 = hr0.x, a01 = hr0.y, a10 = hr1.x, a11 = hr1.y;
                if (mode == 2) {
                    int jg0 = j0 + jc2, jg1 = jg0 + 1;
                    if (!((g == 0) ? (ig0 < jg0) : (ig0 > jg0))) a00 = 0.f;
                    if (!((g == 0) ? (ig0 < jg1) : (ig0 > jg1))) a01 = 0.f;
                    if (!((g == 0) ? (ig1 < jg0) : (ig1 > jg0))) a10 = 0.f;
                    if (!((g == 0) ? (ig1 < jg1) : (ig1 > jg1))) a11 = 0.f;
                }
                __half h00,l00,h01,l01,h10,l10,h11,l11;
                split2h(a00, h00, l00); split2h(a01, h01, l01);
                split2h(a10, h10, l10); split2h(a11, h11, l11);
                Ah2[ip*72 + jc2]     = mkh2(h00, h10);
                Ah2[ip*72 + jc2 + 1] = mkh2(h01, h11);
                Al2[ip*72 + jc2]     = mkh2(l00, l10);
                Al2[ip*72 + jc2 + 1] = mkh2(l01, l11);
            }
            {
                const float* Up = g_U + (size_t)(z*2+g)*(LP*NH*Dm) + (size_t)c*Dm;
                float4 u0 = *(const float4*)&Up[(size_t)(i0s + 2*ip)*1024 + bn];
                float4 u1 = *(const float4*)&Up[(size_t)(i0s + 2*ip + 1)*1024 + bn];
                float r0[4] = {u0.x,u0.y,u0.z,u0.w};
                float r1[4] = {u1.x,u1.y,u1.z,u1.w};
#pragma unroll
                for (int q = 0; q < 4; q++) {
                    __half h0,l0,h1,l1;
                    split2h(r0[q], h0, l0);
                    split2h(r1[q], h1, l1);
                    Bh2[ip*136 + bn + q] = mkh2(h0, h1);
                    Bl2[ip*136 + bn + q] = mkh2(l0, l1);
                }
            }
            __syncthreads();
            unsigned ah[2][4], al_[2][4], bh[4][2], bl_[4][2];
#pragma unroll
            for (int tm = 0; tm < 2; tm++) {
                int r = wm + tm*16 + gr;
                ah[tm][0] = LDU2(&Ah2[gc*72 + r]);
                ah[tm][1] = LDU2(&Ah2[gc*72 + r + 8]);
                ah[tm][2] = LDU2(&Ah2[(gc+4)*72 + r]);
                ah[tm][3] = LDU2(&Ah2[(gc+4)*72 + r + 8]);
                al_[tm][0] = LDU2(&Al2[gc*72 + r]);
                al_[tm][1] = LDU2(&Al2[gc*72 + r + 8]);
                al_[tm][2] = LDU2(&Al2[(gc+4)*72 + r]);
                al_[tm][3] = LDU2(&Al2[(gc+4)*72 + r + 8]);
            }
#pragma unroll
            for (int tn = 0; tn < 4; tn++) {
                int cn = wn + tn*8 + gr;
                bh[tn][0] = LDU2(&Bh2[gc*136 + cn]);
                bh[tn][1] = LDU2(&Bh2[(gc+4)*136 + cn]);
                bl_[tn][0] = LDU2(&Bl2[gc*136 + cn]);
                bl_[tn][1] = LDU2(&Bl2[(gc+4)*136 + cn]);
            }
#pragma unroll
            for (int tm = 0; tm < 2; tm++)
#pragma unroll
                for (int tn = 0; tn < 4; tn++) {
                    mmah(acc[tm][tn], al_[tm], bh[tn]);
                    mmah(acc[tm][tn], ah[tm], bl_[tn]);
                    mmah(acc[tm][tn], ah[tm], bh[tn]);
                }
            __syncthreads();
        }
    }
    float* out = &g_Hp[((size_t)(z*NH + c)*LP + j0)*Dm];
#pragma unroll
    for (int tm = 0; tm < 2; tm++)
#pragma unroll
        for (int tn = 0; tn < 4; tn++) {
            int r  = wm + tm*16 + gr;
            int cn = wn + tn*8 + 2*gc;
            float2 w0; w0.x = acc[tm][tn][0]; w0.y = acc[tm][tn][1];
            float2 w1; w1.x = acc[tm][tn][2]; w1.y = acc[tm][tn][3];
            *(float2*)&out[(size_t)r*Dm + cn]     = w0;
            *(float2*)&out[(size_t)(r+8)*Dm + cn] = w1;
        }
}

// ---------------- q_z = (unary + sum_c Gp + sum_c Hp) * m1 ----------------
__global__ void reduce_qz_kernel() {
    int idx = blockIdx.x * blockDim.x + threadIdx.x;
    if (idx >= Bz*LP*Dm) return;
    int d = idx & 127;
    int zi = idx >> 7;
    int i = zi % LP, z = zi / LP;
    float s = g_unary[idx];
#pragma unroll
    for (int c = 0; c < NH; c++) {
        size_t o = ((size_t)(z*NH + c)*LP + i)*Dm + d;
        s += g_Gp[o] + g_Hp[o];
    }
    g_qz[idx] = s * g_m1[zi];
}

__global__ void out_kernel(float* __restrict__ out) {
    int idx = blockIdx.x * blockDim.x + threadIdx.x;
    if (idx >= Bz*L0c*Dm) return;
    int d = idx & 127;
    int zt = idx >> 7;
    int tt = zt % L0c, z = zt / L0c;
    out[idx] = g_qz[(z*LP + 1 + tt)*Dm + d];
}

extern "C" void kernel_launch(void* const* d_in, const int* in_sizes, int n_in,
                              void* d_out, int out_size) {
    const float* x = nullptr;
    const float* mask = nullptr;
    const float* tern = nullptr;
    for (int i = 0; i < n_in; i++) {
        if (in_sizes[i] == Bz*L0c*Dm)       x    = (const float*)d_in[i];
        else if (in_sizes[i] == Bz*L0c)     mask = (const float*)d_in[i];
        else if (in_sizes[i] == 2*Dm*Dm*NH) tern = (const float*)d_in[i];
    }
    if (!x || !mask || !tern) return;

    prep_unary_kernel<<<(Bz*LP*Dm + 255)/256, 256>>>(x, mask);
    zero_ppad_kernel<<<(128*Dm + 255)/256, 256>>>();
    prep_T_kernel<<<(2*Dm*Dm*NH + 255)/256, 256>>>(tern);

    for (int it = 0; it < NIT; it++) {
        softmax_p_kernel<<<Bz*Lr, 128>>>();
        gemm_uv_kernel<<<dim3(8, 7, 32), 256>>>();
        gemm_f_kernel<<<dim3(7, 28, Bz), 256>>>();
        hsoftmax_kernel<<<Bz*NH*Lr, 128>>>();
        gemm_g_kernel<<<dim3(NH, 7, Bz), 256>>>();
        gemm_hm_kernel<<<dim3(NH, 7, Bz), 256>>>();
        reduce_qz_kernel<<<(Bz*LP*Dm + 255)/256, 256>>>();
    }
    out_kernel<<<(Bz*L0c*Dm + 255)/256, 256>>>((float*)d_out);
}